// round 8
// baseline (speedup 1.0000x reference)
#include <cuda_runtime.h>
#include <cuda_fp16.h>
#include <float.h>
#include <stdint.h>

#define HID 4096
#define SLOTS 8
#define HEADS 8
#define BD 512
#define HD 64
#define BB 4
#define SS 4096
#define NH 64   // HEADS*SLOTS

// Scratch (no allocations allowed)
__device__ float  g_Q[SLOTS * BD];
__device__ float  g_Qk[NH * HID];                // tf32-rounded, scaled by 1/8
__device__ float  g_spart[4 * BB * NH * SS];     // split-K score partials
__device__ __half g_attnh[BB * NH * SS];         // attn probs (fp16)
__device__ __half g_HcT[(size_t)BB * HID * SS];  // fp16 H, transposed+compacted (128MB)
__device__ float  g_apart[2 * BB * NH * HID];    // split-s agg partials
__device__ float  g_mid[BB * SLOTS * BD];
__device__ int    g_sidx[BB * SS];
__device__ int    g_cnt[BB];

#define SPART_SZ (BB * NH * SS)
#define APART_SZ (BB * NH * HID)

__device__ __forceinline__ uint32_t f2tf(float f) {
    uint32_t u;
    asm("cvt.rna.tf32.f32 %0, %1;" : "=r"(u) : "f"(f));
    return u;
}

__device__ __forceinline__ void mma_tf32(float* d, const uint32_t* a, const uint32_t* b) {
    asm volatile(
        "mma.sync.aligned.m16n8k8.row.col.f32.tf32.tf32.f32 "
        "{%0,%1,%2,%3}, {%4,%5,%6,%7}, {%8,%9}, {%0,%1,%2,%3};"
        : "+f"(d[0]), "+f"(d[1]), "+f"(d[2]), "+f"(d[3])
        : "r"(a[0]), "r"(a[1]), "r"(a[2]), "r"(a[3]), "r"(b[0]), "r"(b[1]));
}

__device__ __forceinline__ void mma_f16(float* d, const uint32_t* a, const uint32_t* b) {
    asm volatile(
        "mma.sync.aligned.m16n8k16.row.col.f32.f16.f16.f32 "
        "{%0,%1,%2,%3}, {%4,%5,%6,%7}, {%8,%9}, {%0,%1,%2,%3};"
        : "+f"(d[0]), "+f"(d[1]), "+f"(d[2]), "+f"(d[3])
        : "r"(a[0]), "r"(a[1]), "r"(a[2]), "r"(a[3]), "r"(b[0]), "r"(b[1]));
}

__device__ __forceinline__ void cp16(uint32_t smem_dst, const void* gsrc) {
    asm volatile("cp.async.cg.shared.global [%0], [%1], 16;" :: "r"(smem_dst), "l"(gsrc));
}
#define CP_COMMIT asm volatile("cp.async.commit_group;")
#define CP_WAIT1  asm volatile("cp.async.wait_group 1;")
#define CP_WAIT2  asm volatile("cp.async.wait_group 2;")

// ---------------------------------------------------------------------------
// 0) compaction + zero g_mid
__global__ void k_compact(const int* __restrict__ mask) {
    __shared__ int tsum[256];
    int b = blockIdx.x, tid = threadIdx.x;
    const int* m = mask + b * SS;
    int loc[16], cnt = 0;
    #pragma unroll
    for (int k = 0; k < 16; k++) {
        loc[k] = (m[tid * 16 + k] != 0);
        cnt += loc[k];
    }
    tsum[tid] = cnt;
    __syncthreads();
    for (int o = 1; o < 256; o <<= 1) {
        int v = (tid >= o) ? tsum[tid - o] : 0;
        __syncthreads();
        tsum[tid] += v;
        __syncthreads();
    }
    int off = tsum[tid] - cnt;
    int total = tsum[255];
    int* out = g_sidx + b * SS;
    #pragma unroll
    for (int k = 0; k < 16; k++)
        if (loc[k]) out[off++] = tid * 16 + k;
    if (tid == 0) {
        g_cnt[b] = total;
        int pad = (total + 31) & ~31;
        for (int i = total; i < pad + 32 && i < SS; i++) out[i] = 0;
    }
    float* gm = g_mid + b * 4096;
    #pragma unroll
    for (int k = 0; k < 16; k++) gm[k * 256 + tid] = 0.f;
}

// ---------------------------------------------------------------------------
// 1) Q = memory_slots @ Wq^T
__global__ void k_qproj(const float* __restrict__ ms, const float* __restrict__ Wq) {
    int warp = (blockIdx.x * blockDim.x + threadIdx.x) >> 5;
    int lane = threadIdx.x & 31;
    if (warp >= SLOTS * BD) return;
    int n = warp / BD, c = warp % BD;
    const float* a = ms + n * HID;
    const float* w = Wq + c * HID;
    float acc = 0.f;
    for (int i = lane; i < HID; i += 32) acc += a[i] * w[i];
    #pragma unroll
    for (int off = 16; off; off >>= 1) acc += __shfl_down_sync(0xffffffffu, acc, off);
    if (lane == 0) g_Q[n * BD + c] = acc;
}

// ---------------------------------------------------------------------------
// 2) Qk (tf32-rounded, /8)
__global__ void k_qk(const float* __restrict__ Wk) {
    __shared__ float qs[HD];
    int j = blockIdx.y;
    int h = j >> 3, n = j & 7;
    if (threadIdx.x < HD) qs[threadIdx.x] = g_Q[n * BD + h * HD + threadIdx.x];
    __syncthreads();
    int i = blockIdx.x * blockDim.x + threadIdx.x;
    float acc = 0.f;
    #pragma unroll 8
    for (int d = 0; d < HD; d++) acc += qs[d] * Wk[(h * HD + d) * HID + i];
    g_Qk[j * HID + i] = __uint_as_float(f2tf(acc * 0.125f));
}

// ---------------------------------------------------------------------------
// 3) scores: CTA tile 64cs x 64j, split-K x4, 3-stage cp.async (R6 structure)
//    + emits fp16 transposed H tiles into g_HcT for k_agg.
#define SA 36
#define S_STAGE (128 * SA)
__global__ void __launch_bounds__(256) k_scores(const float* __restrict__ H) {
    extern __shared__ float sm[];
    int b = blockIdx.y;
    int m0 = blockIdx.x * 64;
    int kc = blockIdx.z;
    int cnt = g_cnt[b];
    if (m0 >= cnt) return;
    int tid = threadIdx.x;
    int lane = tid & 31, w = tid >> 5;
    int wm = w & 1, wn = w >> 1;
    int R = wm * 32, C = wn * 16;
    int ar = lane >> 2, ac = lane & 3;

    uint32_t smem_u32 = (uint32_t)__cvta_generic_to_shared(sm);

    float acc[2][2][4];
    #pragma unroll
    for (int t = 0; t < 2; t++)
        #pragma unroll
        for (int n = 0; n < 2; n++)
            #pragma unroll
            for (int q = 0; q < 4; q++) acc[t][n][q] = 0.f;

    int lra = tid >> 3;
    int lca = (tid & 7) * 4;
    int kbase = kc * (HID / 4);

    const float* rowp[2];
    #pragma unroll
    for (int p = 0; p < 2; p++) {
        int s = g_sidx[b * SS + m0 + p * 32 + lra];
        rowp[p] = H + ((size_t)b * SS + s) * HID + kbase + lca;
    }

    auto issue = [&](int stage, int kt) {
        uint32_t base = smem_u32 + stage * S_STAGE * 4;
        #pragma unroll
        for (int p = 0; p < 2; p++) {
            int r = p * 32 + lra;
            cp16(base + (r * SA + lca) * 4, rowp[p] + kt);
        }
        uint32_t bbase = base + 64 * SA * 4;
        #pragma unroll
        for (int p = 0; p < 2; p++) {
            int r = p * 32 + lra;
            cp16(bbase + (r * SA + lca) * 4, &g_Qk[r * HID + kbase + kt + lca]);
        }
    };

    issue(0, 0); CP_COMMIT;
    issue(1, 32); CP_COMMIT;

    const int NIT = HID / 4 / 32;   // 32
    for (int it = 0; it < NIT; it++) {
        CP_WAIT1;
        __syncthreads();
        if (it + 2 < NIT) issue((it + 2) % 3, (it + 2) * 32);
        CP_COMMIT;
        float* As = sm + (it % 3) * S_STAGE;
        float* Bs = As + 64 * SA;
        #pragma unroll
        for (int kk = 0; kk < 32; kk += 8) {
            uint32_t a[2][4], bfrag[2][2];
            #pragma unroll
            for (int t = 0; t < 2; t++) {
                int rb = R + t * 16 + ar;
                a[t][0] = __float_as_uint(As[rb * SA + kk + ac]);
                a[t][1] = __float_as_uint(As[(rb + 8) * SA + kk + ac]);
                a[t][2] = __float_as_uint(As[rb * SA + kk + ac + 4]);
                a[t][3] = __float_as_uint(As[(rb + 8) * SA + kk + ac + 4]);
            }
            #pragma unroll
            for (int n = 0; n < 2; n++) {
                int cb = C + n * 8 + ar;
                bfrag[n][0] = __float_as_uint(Bs[cb * SA + kk + ac]);
                bfrag[n][1] = __float_as_uint(Bs[cb * SA + kk + ac + 4]);
            }
            #pragma unroll
            for (int t = 0; t < 2; t++)
                #pragma unroll
                for (int n = 0; n < 2; n++)
                    mma_tf32(acc[t][n], a[t], bfrag[n]);
        }
        // emit fp16 transposed tile: g_HcT[(b*HID + kbase + it*32 + k)*SS + m0 + cs]
        {
            int wk = tid >> 5;              // 0..7 (k row within pass)
            int cs2 = (tid & 31) * 2;       // cs pair
            #pragma unroll
            for (int p = 0; p < 4; p++) {
                int k = p * 8 + wk;
                float v0 = As[cs2 * SA + k];
                float v1 = As[(cs2 + 1) * SA + k];
                __half2 hv = __floats2half2_rn(v0, v1);
                *(__half2*)&g_HcT[((size_t)b * HID + kbase + it * 32 + k) * SS + m0 + cs2] = hv;
            }
        }
        // next iteration's top barrier protects buffer reuse (emit reads included)
    }
    __syncthreads();

    float* Cs = sm;
    #pragma unroll
    for (int t = 0; t < 2; t++) {
        #pragma unroll
        for (int n = 0; n < 2; n++) {
            int row = R + t * 16 + ar;
            int col = C + n * 8 + 2 * ac;
            Cs[col * 65 + row]            = acc[t][n][0];
            Cs[(col + 1) * 65 + row]      = acc[t][n][1];
            Cs[col * 65 + row + 8]        = acc[t][n][2];
            Cs[(col + 1) * 65 + row + 8]  = acc[t][n][3];
        }
    }
    __syncthreads();
    float* dst = g_spart + kc * SPART_SZ;
    #pragma unroll
    for (int l = 0; l < 16; l++) {
        int e = l * 256 + tid;
        int j = e >> 6, m = e & 63;
        dst[((b * NH + j) << 12) + m0 + m] = Cs[j * 65 + m];
    }
}

// ---------------------------------------------------------------------------
// 4) softmax: sum 4 split-K partials, softmax over compacted prefix -> fp16
__global__ void k_softmax() {
    __shared__ float red[256];
    int row = blockIdx.x;
    int b = row >> 6;
    int cnt = g_cnt[b];
    const float* p0 = g_spart + row * SS;
    __half* sc = g_attnh + (size_t)row * SS;
    int tid = threadIdx.x;
    float v[16];
    float mx = -FLT_MAX;
    #pragma unroll
    for (int k = 0; k < 16; k++) {
        int s = k * 256 + tid;
        float val = -FLT_MAX;
        if (s < cnt)
            val = p0[s] + p0[SPART_SZ + s] + p0[2 * SPART_SZ + s] + p0[3 * SPART_SZ + s];
        v[k] = val;
        mx = fmaxf(mx, val);
    }
    red[tid] = mx; __syncthreads();
    for (int o = 128; o; o >>= 1) { if (tid < o) red[tid] = fmaxf(red[tid], red[tid + o]); __syncthreads(); }
    mx = red[0]; __syncthreads();
    float sum = 0.f;
    #pragma unroll
    for (int k = 0; k < 16; k++) {
        int s = k * 256 + tid;
        v[k] = (s < cnt) ? __expf(v[k] - mx) : 0.f;
        sum += v[k];
    }
    red[tid] = sum; __syncthreads();
    for (int o = 128; o; o >>= 1) { if (tid < o) red[tid] += red[tid + o]; __syncthreads(); }
    float inv = 1.f / red[0];
    #pragma unroll
    for (int k = 0; k < 16; k++) sc[k * 256 + tid] = __float2half(v[k] * inv);
}

// ---------------------------------------------------------------------------
// 5) agg (fp16 MMA): CTA tile 64j x 64i, split-s x2, 4-stage cp.async
//    A = attn fp16 [j][s], B = g_HcT fp16 [i][s] (both K-major, k=s)
#define HSTR 40                         // halves per row (32 + 8 pad)
#define GA_BYTES (64 * HSTR * 2)        // 5120 B per tile
#define G_STAGE_BYTES (2 * GA_BYTES)    // 10240 B per stage
__global__ void __launch_bounds__(256, 5) k_agg() {
    extern __shared__ char smc[];
    int tid = threadIdx.x;
    int lane = tid & 31, w = tid >> 5;
    int wm = w & 1, wn = w >> 1;
    int R = wm * 32, C = wn * 16;
    int b = blockIdx.y;
    int i0 = blockIdx.x * 64;
    int sc_id = blockIdx.z;
    int ar = lane >> 2, ac = lane & 3;
    int cnt = g_cnt[b];
    int NIT_total = (cnt + 31) >> 5;
    int half = (NIT_total + 1) >> 1;
    int it0 = sc_id * half;
    int it1 = min(NIT_total, it0 + half);

    uint32_t smem_u32 = (uint32_t)__cvta_generic_to_shared(smc);
    const uint32_t* smw = (const uint32_t*)smc;

    float acc[2][2][4];
    #pragma unroll
    for (int t = 0; t < 2; t++)
        #pragma unroll
        for (int n = 0; n < 2; n++)
            #pragma unroll
            for (int q = 0; q < 4; q++) acc[t][n][q] = 0.f;

    const __half* A  = g_attnh + (size_t)b * NH * SS;
    const __half* Bm = g_HcT + (size_t)b * HID * SS + (size_t)i0 * SS;

    int rrow = tid >> 2;            // 0..63
    int rc16 = (tid & 3) * 16;      // byte offset within 64B row
    int rc8  = (tid & 3) * 8;       // halves offset

    auto issue = [&](int stage, int it) {
        int st = it * 32;
        uint32_t base = smem_u32 + stage * G_STAGE_BYTES;
        cp16(base + rrow * (HSTR * 2) + rc16, &A[(size_t)rrow * SS + st + rc8]);
        uint32_t bbase = base + GA_BYTES;
        cp16(bbase + rrow * (HSTR * 2) + rc16, &Bm[(size_t)rrow * SS + st + rc8]);
    };

    if (it0 < it1) {
        if (it0 < it1) issue(0, it0); CP_COMMIT;
        if (it0 + 1 < it1) issue(1, it0 + 1); CP_COMMIT;
        if (it0 + 2 < it1) issue(2, it0 + 2); CP_COMMIT;
        for (int it = it0; it < it1; it++) {
            CP_WAIT2;
            __syncthreads();
            if (it + 3 < it1) issue((it - it0 + 3) & 3, it + 3);
            CP_COMMIT;
            const uint32_t* As = smw + ((it - it0) & 3) * (G_STAGE_BYTES / 4);
            const uint32_t* Bs = As + GA_BYTES / 4;
            #pragma unroll
            for (int ks = 0; ks < 2; ks++) {
                uint32_t a[2][4], bfr[2][2];
                int kb = ks * 8;   // word offset for this k16 step
                #pragma unroll
                for (int t = 0; t < 2; t++) {
                    int rb = R + t * 16 + ar;
                    a[t][0] = As[rb * (HSTR / 2) + kb + ac];
                    a[t][1] = As[(rb + 8) * (HSTR / 2) + kb + ac];
                    a[t][2] = As[rb * (HSTR / 2) + kb + 4 + ac];
                    a[t][3] = As[(rb + 8) * (HSTR / 2) + kb + 4 + ac];
                }
                #pragma unroll
                for (int n = 0; n < 2; n++) {
                    int cb = C + n * 8 + ar;
                    bfr[n][0] = Bs[cb * (HSTR / 2) + kb + ac];
                    bfr[n][1] = Bs[cb * (HSTR / 2) + kb + 4 + ac];
                }
                #pragma unroll
                for (int t = 0; t < 2; t++)
                    #pragma unroll
                    for (int n = 0; n < 2; n++)
                        mma_f16(acc[t][n], a[t], bfr[n]);
            }
        }
    }

    float* dst = g_apart + sc_id * APART_SZ;
    #pragma unroll
    for (int t = 0; t < 2; t++) {
        #pragma unroll
        for (int n = 0; n < 2; n++) {
            int j = R + t * 16 + ar;
            int i = C + n * 8 + 2 * ac;
            float2 v0 = make_float2(acc[t][n][0], acc[t][n][1]);
            float2 v1 = make_float2(acc[t][n][2], acc[t][n][3]);
            *(float2*)&dst[(size_t)(b * NH + j) * HID + i0 + i]     = v0;
            *(float2*)&dst[(size_t)(b * NH + j + 8) * HID + i0 + i] = v1;
        }
    }
}

// ---------------------------------------------------------------------------
// 6) mid, split-K x4 with atomic epilogue; sums the 2 agg partials
__global__ void k_mid(const float* __restrict__ Wv) {
    __shared__ float As[8][65];
    __shared__ float Bs[64][65];
    int h = blockIdx.x, b = blockIdx.y, kc = blockIdx.z;
    int tid = threadIdx.x;
    float acc0 = 0.f, acc1 = 0.f;
    int o0 = tid, o1 = tid + 256;
    int n0 = o0 >> 6, d0 = o0 & 63;
    int n1 = o1 >> 6, d1 = o1 & 63;
    int k0 = kc * (HID / 4), k1 = k0 + HID / 4;
    for (int kt = k0; kt < k1; kt += 64) {
        {
            int e = tid; int r = e >> 6, c = e & 63;
            size_t ix = (size_t)(b * NH + h * SLOTS + r) * HID + kt + c;
            As[r][c] = g_apart[ix] + g_apart[APART_SZ + ix];
            e = tid + 256; r = e >> 6; c = e & 63;
            ix = (size_t)(b * NH + h * SLOTS + r) * HID + kt + c;
            As[r][c] = g_apart[ix] + g_apart[APART_SZ + ix];
        }
        #pragma unroll
        for (int l = 0; l < 16; l++) {
            int e = tid + l * 256;
            int r = e >> 6, c = e & 63;
            Bs[r][c] = Wv[(h * HD + r) * HID + kt + c];
        }
        __syncthreads();
        #pragma unroll
        for (int k = 0; k < 64; k++) {
            acc0 += As[n0][k] * Bs[d0][k];
            acc1 += As[n1][k] * Bs[d1][k];
        }
        __syncthreads();
    }
    atomicAdd(&g_mid[(b * SLOTS + n0) * BD + h * HD + d0], acc0);
    atomicAdd(&g_mid[(b * SLOTS + n1) * BD + h * HD + d1], acc1);
}

// ---------------------------------------------------------------------------
// 7) final, o-tile 64
__global__ void k_final(const float* __restrict__ Wo, float* __restrict__ out) {
    __shared__ float As[32][65];
    __shared__ float Bs[64][65];
    int tid = threadIdx.x;
    int tx = tid & 15, ty = tid >> 4;
    int o0 = blockIdx.x * 64;
    float acc[2][4] = {};
    for (int kt = 0; kt < BD; kt += 64) {
        #pragma unroll
        for (int l = 0; l < 8; l++) {
            int e = tid + l * 256;
            int r = e >> 6, c = e & 63;
            As[r][c] = g_mid[r * BD + kt + c];
        }
        #pragma unroll
        for (int l = 0; l < 16; l++) {
            int e = tid + l * 256;
            int r = e >> 6, c = e & 63;
            Bs[r][c] = Wo[(o0 + r) * BD + kt + c];
        }
        __syncthreads();
        #pragma unroll
        for (int k = 0; k < 64; k++) {
            float a[2], bb[4];
            #pragma unroll
            for (int x = 0; x < 2; x++) a[x] = As[ty * 2 + x][k];
            #pragma unroll
            for (int y = 0; y < 4; y++) bb[y] = Bs[tx * 4 + y][k];
            #pragma unroll
            for (int x = 0; x < 2; x++)
                #pragma unroll
                for (int y = 0; y < 4; y++) acc[x][y] += a[x] * bb[y];
        }
        __syncthreads();
    }
    #pragma unroll
    for (int x = 0; x < 2; x++)
        #pragma unroll
        for (int y = 0; y < 4; y++)
            out[(ty * 2 + x) * HID + o0 + tx * 4 + y] = acc[x][y];
}

// ---------------------------------------------------------------------------
extern "C" void kernel_launch(void* const* d_in, const int* in_sizes, int n_in,
                              void* d_out, int out_size) {
    const float* H    = (const float*)d_in[0];
    const int*   mask = (const int*)d_in[1];
    const float* ms   = (const float*)d_in[2];
    const float* Wq   = (const float*)d_in[3];
    const float* Wk   = (const float*)d_in[4];
    const float* Wv   = (const float*)d_in[5];
    const float* Wo   = (const float*)d_in[6];
    float* out = (float*)d_out;

    static int attr_done = 0;
    if (!attr_done) {
        cudaFuncSetAttribute(k_scores, cudaFuncAttributeMaxDynamicSharedMemorySize,
                             3 * S_STAGE * 4);
        attr_done = 1;
    }

    k_compact<<<BB, 256>>>(mask);
    k_qproj <<<512, 256>>>(ms, Wq);
    k_qk    <<<dim3(HID / 256, NH), 256>>>(Wk);
    k_scores<<<dim3(SS / 64, BB, 4), 256, 3 * S_STAGE * 4>>>(H);
    k_softmax<<<BB * NH, 256>>>();
    k_agg   <<<dim3(HID / 64, BB, 2), 256, 4 * G_STAGE_BYTES>>>();
    k_mid   <<<dim3(HEADS, BB, 4), 256>>>(Wv);
    k_final <<<HID / 64, 256>>>(Wo, out);
}

// round 9
// speedup vs baseline: 1.1024x; 1.1024x over previous
#include <cuda_runtime.h>
#include <cuda_fp16.h>
#include <float.h>
#include <stdint.h>

#define HID 4096
#define SLOTS 8
#define HEADS 8
#define BD 512
#define HD 64
#define BB 4
#define SS 4096
#define NH 64   // HEADS*SLOTS

// Scratch (no allocations allowed)
__device__ float  g_Q[SLOTS * BD];
__device__ __half g_Qk16[NH * HID];              // fp16, scaled by 1/8
__device__ __half g_H16c[(size_t)BB * SS * HID]; // fp16 H, compacted rows (128MB)
__device__ float  g_spart[4 * BB * NH * SS];     // split-K score partials
__device__ __half g_attnh[BB * NH * SS];         // attn probs (fp16)
__device__ float  g_apart[2 * BB * NH * HID];    // split-s agg partials
__device__ float  g_mid[BB * SLOTS * BD];
__device__ int    g_sidx[BB * SS];
__device__ int    g_cnt[BB];

#define SPART_SZ (BB * NH * SS)
#define APART_SZ (BB * NH * HID)

__device__ __forceinline__ void mma_f16(float* d, const uint32_t* a, const uint32_t* b) {
    asm volatile(
        "mma.sync.aligned.m16n8k16.row.col.f32.f16.f16.f32 "
        "{%0,%1,%2,%3}, {%4,%5,%6,%7}, {%8,%9}, {%0,%1,%2,%3};"
        : "+f"(d[0]), "+f"(d[1]), "+f"(d[2]), "+f"(d[3])
        : "r"(a[0]), "r"(a[1]), "r"(a[2]), "r"(a[3]), "r"(b[0]), "r"(b[1]));
}

__device__ __forceinline__ void cp16(uint32_t smem_dst, const void* gsrc) {
    asm volatile("cp.async.cg.shared.global [%0], [%1], 16;" :: "r"(smem_dst), "l"(gsrc));
}
#define CP_COMMIT asm volatile("cp.async.commit_group;")
#define CP_WAIT2  asm volatile("cp.async.wait_group 2;")
#define CP_WAIT0  asm volatile("cp.async.wait_group 0;")

// ---------------------------------------------------------------------------
// 0) compaction + zero g_mid
__global__ void k_compact(const int* __restrict__ mask) {
    __shared__ int tsum[256];
    int b = blockIdx.x, tid = threadIdx.x;
    const int* m = mask + b * SS;
    int loc[16], cnt = 0;
    #pragma unroll
    for (int k = 0; k < 16; k++) {
        loc[k] = (m[tid * 16 + k] != 0);
        cnt += loc[k];
    }
    tsum[tid] = cnt;
    __syncthreads();
    for (int o = 1; o < 256; o <<= 1) {
        int v = (tid >= o) ? tsum[tid - o] : 0;
        __syncthreads();
        tsum[tid] += v;
        __syncthreads();
    }
    int off = tsum[tid] - cnt;
    int total = tsum[255];
    int* out = g_sidx + b * SS;
    #pragma unroll
    for (int k = 0; k < 16; k++)
        if (loc[k]) out[off++] = tid * 16 + k;
    if (tid == 0) g_cnt[b] = total;
    float* gm = g_mid + b * 4096;
    #pragma unroll
    for (int k = 0; k < 16; k++) gm[k * 256 + tid] = 0.f;
}

// ---------------------------------------------------------------------------
// 1) Q = memory_slots @ Wq^T
__global__ void k_qproj(const float* __restrict__ ms, const float* __restrict__ Wq) {
    int warp = (blockIdx.x * blockDim.x + threadIdx.x) >> 5;
    int lane = threadIdx.x & 31;
    if (warp >= SLOTS * BD) return;
    int n = warp / BD, c = warp % BD;
    const float* a = ms + n * HID;
    const float* w = Wq + c * HID;
    float acc = 0.f;
    for (int i = lane; i < HID; i += 32) acc += a[i] * w[i];
    #pragma unroll
    for (int off = 16; off; off >>= 1) acc += __shfl_down_sync(0xffffffffu, acc, off);
    if (lane == 0) g_Q[n * BD + c] = acc;
}

// ---------------------------------------------------------------------------
// 2) Qk16[j][i] = fp16( (1/8) * sum_d Q[n][h*64+d] * Wk[h*64+d][i] )
__global__ void k_qk(const float* __restrict__ Wk) {
    __shared__ float qs[HD];
    int j = blockIdx.y;
    int h = j >> 3, n = j & 7;
    if (threadIdx.x < HD) qs[threadIdx.x] = g_Q[n * BD + h * HD + threadIdx.x];
    __syncthreads();
    int i = blockIdx.x * blockDim.x + threadIdx.x;
    float acc = 0.f;
    #pragma unroll 8
    for (int d = 0; d < HD; d++) acc += qs[d] * Wk[(h * HD + d) * HID + i];
    g_Qk16[j * HID + i] = __float2half(acc * 0.125f);
}

// ---------------------------------------------------------------------------
// 2b) conv: gather unmasked H rows -> fp16 compacted; zero-fill 64-row pad
__global__ void k_conv(const float* __restrict__ H) {
    int b = blockIdx.y;
    int r0 = blockIdx.x * 8;
    int cnt = g_cnt[b];
    int tid = threadIdx.x;
    for (int p = 0; p < 8; p++) {
        int cs = r0 + p;
        if (cs < cnt) {
            int s = g_sidx[b * SS + cs];
            const float4* src = (const float4*)(H + ((size_t)b * SS + s) * HID);
            uint2* dst = (uint2*)(g_H16c + ((size_t)b * SS + cs) * HID);
            #pragma unroll
            for (int q = 0; q < 4; q++) {
                int i = q * 256 + tid;
                float4 v = src[i];
                __half2 h0 = __floats2half2_rn(v.x, v.y);
                __half2 h1 = __floats2half2_rn(v.z, v.w);
                uint2 pk;
                pk.x = *(uint32_t*)&h0;
                pk.y = *(uint32_t*)&h1;
                dst[i] = pk;
            }
        } else if (cs < cnt + 64 && cs < SS) {
            uint2* dst = (uint2*)(g_H16c + ((size_t)b * SS + cs) * HID);
            uint2 z = make_uint2(0u, 0u);
            #pragma unroll
            for (int q = 0; q < 4; q++) dst[q * 256 + tid] = z;
        }
    }
}

// ---------------------------------------------------------------------------
// 3) scores fp16: C[cs][j] = H16c[cs,:] . Qk16[j,:], tile 64x64, split-K x4,
//    4-stage cp.async, manual LDS fragments (R8-agg-proven pattern)
#define QW 20                      // words per smem tile row (40 halves)
#define SC_TILE_B (64 * QW * 4)    // 5120 B
#define SC_STAGE_B (2 * SC_TILE_B) // 10240 B
__global__ void __launch_bounds__(256) k_scores() {
    extern __shared__ char smc[];
    int b = blockIdx.y, m0 = blockIdx.x * 64, kc = blockIdx.z;
    int cnt = g_cnt[b];
    if (m0 >= cnt) return;
    int tid = threadIdx.x, lane = tid & 31, w = tid >> 5;
    int wm = w & 1, wn = w >> 1;
    int R = wm * 32, C = wn * 16;
    int ar = lane >> 2, ac = lane & 3;
    uint32_t smem_u32 = (uint32_t)__cvta_generic_to_shared(smc);
    const uint32_t* smw = (const uint32_t*)smc;

    float acc[2][2][4];
    #pragma unroll
    for (int t = 0; t < 2; t++)
        #pragma unroll
        for (int n = 0; n < 2; n++)
            #pragma unroll
            for (int q = 0; q < 4; q++) acc[t][n][q] = 0.f;

    int rrow = tid >> 2;
    int rc8 = (tid & 3) * 8;
    const __half* Asrc = g_H16c + ((size_t)b * SS + m0) * HID + kc * 1024;
    const __half* Bsrc = g_Qk16 + kc * 1024;

    auto issue = [&](int stage, int it) {
        int st = it * 32;
        uint32_t base = smem_u32 + stage * SC_STAGE_B;
        cp16(base + rrow * 80 + (tid & 3) * 16, Asrc + (size_t)rrow * HID + st + rc8);
        cp16(base + SC_TILE_B + rrow * 80 + (tid & 3) * 16, Bsrc + (size_t)rrow * HID + st + rc8);
    };

    const int NIT = 32;
    issue(0, 0); CP_COMMIT;
    issue(1, 1); CP_COMMIT;
    issue(2, 2); CP_COMMIT;
    for (int it = 0; it < NIT; it++) {
        CP_WAIT2;
        __syncthreads();
        if (it + 3 < NIT) issue((it + 3) & 3, it + 3);
        CP_COMMIT;
        const uint32_t* As = smw + ((it & 3) * SC_STAGE_B) / 4;
        const uint32_t* Bs = As + SC_TILE_B / 4;
        #pragma unroll
        for (int ks = 0; ks < 2; ks++) {
            int kb = ks * 8;
            uint32_t a[2][4], bf[2][2];
            #pragma unroll
            for (int t = 0; t < 2; t++) {
                int rb = R + t * 16 + ar;
                a[t][0] = As[rb * QW + kb + ac];
                a[t][1] = As[(rb + 8) * QW + kb + ac];
                a[t][2] = As[rb * QW + kb + 4 + ac];
                a[t][3] = As[(rb + 8) * QW + kb + 4 + ac];
            }
            #pragma unroll
            for (int n = 0; n < 2; n++) {
                int cb = C + n * 8 + ar;
                bf[n][0] = Bs[cb * QW + kb + ac];
                bf[n][1] = Bs[cb * QW + kb + 4 + ac];
            }
            #pragma unroll
            for (int t = 0; t < 2; t++)
                #pragma unroll
                for (int n = 0; n < 2; n++)
                    mma_f16(acc[t][n], a[t], bf[n]);
        }
    }
    CP_WAIT0;
    __syncthreads();

    // transpose-stage C (64cs x 64j) -> g_spart[kc][(b,j)][cs]
    float* Cs = (float*)smc;
    #pragma unroll
    for (int t = 0; t < 2; t++) {
        #pragma unroll
        for (int n = 0; n < 2; n++) {
            int row = R + t * 16 + ar;
            int col = C + n * 8 + 2 * ac;
            Cs[col * 65 + row]            = acc[t][n][0];
            Cs[(col + 1) * 65 + row]      = acc[t][n][1];
            Cs[col * 65 + row + 8]        = acc[t][n][2];
            Cs[(col + 1) * 65 + row + 8]  = acc[t][n][3];
        }
    }
    __syncthreads();
    float* dst = g_spart + kc * SPART_SZ;
    #pragma unroll
    for (int l = 0; l < 16; l++) {
        int e = l * 256 + tid;
        int j = e >> 6, m = e & 63;
        dst[((b * NH + j) << 12) + m0 + m] = Cs[j * 65 + m];
    }
}

// ---------------------------------------------------------------------------
// 4) softmax: sum 4 split-K partials, softmax over compacted prefix -> fp16
__global__ void k_softmax() {
    __shared__ float red[256];
    int row = blockIdx.x;
    int b = row >> 6;
    int cnt = g_cnt[b];
    const float* p0 = g_spart + row * SS;
    __half* sc = g_attnh + (size_t)row * SS;
    int tid = threadIdx.x;
    float v[16];
    float mx = -FLT_MAX;
    #pragma unroll
    for (int k = 0; k < 16; k++) {
        int s = k * 256 + tid;
        float val = -FLT_MAX;
        if (s < cnt)
            val = p0[s] + p0[SPART_SZ + s] + p0[2 * SPART_SZ + s] + p0[3 * SPART_SZ + s];
        v[k] = val;
        mx = fmaxf(mx, val);
    }
    red[tid] = mx; __syncthreads();
    for (int o = 128; o; o >>= 1) { if (tid < o) red[tid] = fmaxf(red[tid], red[tid + o]); __syncthreads(); }
    mx = red[0]; __syncthreads();
    float sum = 0.f;
    #pragma unroll
    for (int k = 0; k < 16; k++) {
        int s = k * 256 + tid;
        v[k] = (s < cnt) ? __expf(v[k] - mx) : 0.f;
        sum += v[k];
    }
    red[tid] = sum; __syncthreads();
    for (int o = 128; o; o >>= 1) { if (tid < o) red[tid] += red[tid + o]; __syncthreads(); }
    float inv = 1.f / red[0];
    #pragma unroll
    for (int k = 0; k < 16; k++) sc[k * 256 + tid] = __float2half(v[k] * inv);
}

// ---------------------------------------------------------------------------
// 5) agg fp16: tile 64j x 64i, split-s x2, A=attn (manual frags),
//    B=H16c [s][i] via ldmatrix.x4.trans
#define AGA_B (64 * QW * 4)          // 5120 B attn tile
#define AGB_W 36                     // words per H-tile row (72 halves)
#define AGB_B (32 * AGB_W * 4)       // 4608 B
#define AG_STAGE_B (AGA_B + AGB_B)   // 9728 B
__global__ void __launch_bounds__(256) k_agg() {
    extern __shared__ char smc[];
    int tid = threadIdx.x, lane = tid & 31, w = tid >> 5;
    int wm = w & 1, wn = w >> 1;
    int R = wm * 32, C = wn * 16;
    int b = blockIdx.y;
    int i0 = blockIdx.x * 64;
    int sc_id = blockIdx.z;
    int ar = lane >> 2, ac = lane & 3;
    int cnt = g_cnt[b];
    int NIT_total = (cnt + 31) >> 5;
    int half = (NIT_total + 1) >> 1;
    int it0 = sc_id * half;
    int it1 = min(NIT_total, it0 + half);

    uint32_t smem_u32 = (uint32_t)__cvta_generic_to_shared(smc);
    const uint32_t* smw = (const uint32_t*)smc;

    float acc[2][2][4];
    #pragma unroll
    for (int t = 0; t < 2; t++)
        #pragma unroll
        for (int n = 0; n < 2; n++)
            #pragma unroll
            for (int q = 0; q < 4; q++) acc[t][n][q] = 0.f;

    const __half* Asrc = g_attnh + (size_t)b * NH * SS;
    const __half* Bsrc = g_H16c + (size_t)b * SS * HID + i0;

    int rrow = tid >> 2;
    int rc8 = (tid & 3) * 8;
    int brow = tid >> 3;
    int bc8 = (tid & 7) * 8;

    auto issue = [&](int stage, int it) {
        int st = it * 32;
        uint32_t base = smem_u32 + stage * AG_STAGE_B;
        cp16(base + rrow * 80 + (tid & 3) * 16, Asrc + (size_t)rrow * SS + st + rc8);
        cp16(base + AGA_B + brow * 144 + (tid & 7) * 16, Bsrc + (size_t)(st + brow) * HID + bc8);
    };

    // ldmatrix lane addressing for B (x4.trans): lanes 0-7 k0-7/n0, 8-15 k8-15/n0,
    // 16-23 k0-7/n1, 24-31 k8-15/n1
    int lrow = lane & 15;
    int lcol = C + (lane >> 4) * 8;

    if (it0 < it1) {
        issue(0, it0); CP_COMMIT;
        if (it0 + 1 < it1) issue(1, it0 + 1); CP_COMMIT;
        if (it0 + 2 < it1) issue(2, it0 + 2); CP_COMMIT;
        for (int it = it0; it < it1; it++) {
            CP_WAIT2;
            __syncthreads();
            if (it + 3 < it1) issue((it - it0 + 3) & 3, it + 3);
            CP_COMMIT;
            int stg = (it - it0) & 3;
            const uint32_t* As = smw + (stg * AG_STAGE_B) / 4;
            uint32_t bbase = smem_u32 + stg * AG_STAGE_B + AGA_B;
            #pragma unroll
            for (int ks = 0; ks < 2; ks++) {
                int kb = ks * 8;
                uint32_t a[2][4];
                #pragma unroll
                for (int t = 0; t < 2; t++) {
                    int rb = R + t * 16 + ar;
                    a[t][0] = As[rb * QW + kb + ac];
                    a[t][1] = As[(rb + 8) * QW + kb + ac];
                    a[t][2] = As[rb * QW + kb + 4 + ac];
                    a[t][3] = As[(rb + 8) * QW + kb + 4 + ac];
                }
                uint32_t baddr = bbase + (uint32_t)((ks * 16 + lrow) * 144 + lcol * 2);
                uint32_t rb0, rb1, rb2, rb3;
                asm volatile(
                    "ldmatrix.sync.aligned.m8n8.x4.trans.shared.b16 {%0,%1,%2,%3}, [%4];"
                    : "=r"(rb0), "=r"(rb1), "=r"(rb2), "=r"(rb3) : "r"(baddr));
                uint32_t bf0[2] = {rb0, rb1};
                uint32_t bf1[2] = {rb2, rb3};
                #pragma unroll
                for (int t = 0; t < 2; t++) {
                    mma_f16(acc[t][0], a[t], bf0);
                    mma_f16(acc[t][1], a[t], bf1);
                }
            }
        }
    }

    float* dst = g_apart + sc_id * APART_SZ;
    #pragma unroll
    for (int t = 0; t < 2; t++) {
        #pragma unroll
        for (int n = 0; n < 2; n++) {
            int j = R + t * 16 + ar;
            int i = C + n * 8 + 2 * ac;
            float2 v0 = make_float2(acc[t][n][0], acc[t][n][1]);
            float2 v1 = make_float2(acc[t][n][2], acc[t][n][3]);
            *(float2*)&dst[(size_t)(b * NH + j) * HID + i0 + i]     = v0;
            *(float2*)&dst[(size_t)(b * NH + j + 8) * HID + i0 + i] = v1;
        }
    }
}

// ---------------------------------------------------------------------------
// 6) mid, split-K x4 with atomic epilogue; sums the 2 agg partials
__global__ void k_mid(const float* __restrict__ Wv) {
    __shared__ float As[8][65];
    __shared__ float Bs[64][65];
    int h = blockIdx.x, b = blockIdx.y, kc = blockIdx.z;
    int tid = threadIdx.x;
    float acc0 = 0.f, acc1 = 0.f;
    int o0 = tid, o1 = tid + 256;
    int n0 = o0 >> 6, d0 = o0 & 63;
    int n1 = o1 >> 6, d1 = o1 & 63;
    int k0 = kc * (HID / 4), k1 = k0 + HID / 4;
    for (int kt = k0; kt < k1; kt += 64) {
        {
            int e = tid; int r = e >> 6, c = e & 63;
            size_t ix = (size_t)(b * NH + h * SLOTS + r) * HID + kt + c;
            As[r][c] = g_apart[ix] + g_apart[APART_SZ + ix];
            e = tid + 256; r = e >> 6; c = e & 63;
            ix = (size_t)(b * NH + h * SLOTS + r) * HID + kt + c;
            As[r][c] = g_apart[ix] + g_apart[APART_SZ + ix];
        }
        #pragma unroll
        for (int l = 0; l < 16; l++) {
            int e = tid + l * 256;
            int r = e >> 6, c = e & 63;
            Bs[r][c] = Wv[(h * HD + r) * HID + kt + c];
        }
        __syncthreads();
        #pragma unroll
        for (int k = 0; k < 64; k++) {
            acc0 += As[n0][k] * Bs[d0][k];
            acc1 += As[n1][k] * Bs[d1][k];
        }
        __syncthreads();
    }
    atomicAdd(&g_mid[(b * SLOTS + n0) * BD + h * HD + d0], acc0);
    atomicAdd(&g_mid[(b * SLOTS + n1) * BD + h * HD + d1], acc1);
}

// ---------------------------------------------------------------------------
// 7) final, o-tile 64
__global__ void k_final(const float* __restrict__ Wo, float* __restrict__ out) {
    __shared__ float As[32][65];
    __shared__ float Bs[64][65];
    int tid = threadIdx.x;
    int tx = tid & 15, ty = tid >> 4;
    int o0 = blockIdx.x * 64;
    float acc[2][4] = {};
    for (int kt = 0; kt < BD; kt += 64) {
        #pragma unroll
        for (int l = 0; l < 8; l++) {
            int e = tid + l * 256;
            int r = e >> 6, c = e & 63;
            As[r][c] = g_mid[r * BD + kt + c];
        }
        #pragma unroll
        for (int l = 0; l < 16; l++) {
            int e = tid + l * 256;
            int r = e >> 6, c = e & 63;
            Bs[r][c] = Wo[(o0 + r) * BD + kt + c];
        }
        __syncthreads();
        #pragma unroll
        for (int k = 0; k < 64; k++) {
            float a[2], bb[4];
            #pragma unroll
            for (int x = 0; x < 2; x++) a[x] = As[ty * 2 + x][k];
            #pragma unroll
            for (int y = 0; y < 4; y++) bb[y] = Bs[tx * 4 + y][k];
            #pragma unroll
            for (int x = 0; x < 2; x++)
                #pragma unroll
                for (int y = 0; y < 4; y++) acc[x][y] += a[x] * bb[y];
        }
        __syncthreads();
    }
    #pragma unroll
    for (int x = 0; x < 2; x++)
        #pragma unroll
        for (int y = 0; y < 4; y++)
            out[(ty * 2 + x) * HID + o0 + tx * 4 + y] = acc[x][y];
}

// ---------------------------------------------------------------------------
extern "C" void kernel_launch(void* const* d_in, const int* in_sizes, int n_in,
                              void* d_out, int out_size) {
    const float* H    = (const float*)d_in[0];
    const int*   mask = (const int*)d_in[1];
    const float* ms   = (const float*)d_in[2];
    const float* Wq   = (const float*)d_in[3];
    const float* Wk   = (const float*)d_in[4];
    const float* Wv   = (const float*)d_in[5];
    const float* Wo   = (const float*)d_in[6];
    float* out = (float*)d_out;

    k_compact<<<BB, 256>>>(mask);
    k_qproj <<<512, 256>>>(ms, Wq);
    k_qk    <<<dim3(HID / 256, NH), 256>>>(Wk);
    k_conv  <<<dim3(SS / 8, BB), 256>>>(H);
    k_scores<<<dim3(SS / 64, BB, 4), 256, 4 * SC_STAGE_B>>>();
    k_softmax<<<BB * NH, 256>>>();
    k_agg   <<<dim3(HID / 64, BB, 2), 256, 4 * AG_STAGE_B>>>();
    k_mid   <<<dim3(HEADS, BB, 4), 256>>>(Wv);
    k_final <<<HID / 64, 256>>>(Wo, out);
}

// round 10
// speedup vs baseline: 1.1658x; 1.0575x over previous
#include <cuda_runtime.h>
#include <cuda_fp16.h>
#include <float.h>
#include <stdint.h>

#define HID 4096
#define SLOTS 8
#define HEADS 8
#define BD 512
#define HD 64
#define BB 4
#define SS 4096
#define NH 64   // HEADS*SLOTS

// Scratch (no allocations allowed)
__device__ float  g_Q[SLOTS * BD];
__device__ __half g_Qk16[NH * HID];              // fp16, scaled by 1/8
__device__ __half g_H16c[(size_t)BB * SS * HID]; // fp16 H, compacted rows
__device__ __half g_spart16[4 * BB * NH * SS];   // split-K score partials (fp16)
__device__ __half g_attnh[BB * NH * SS];         // attn probs (fp16)
__device__ float  g_apart[2 * BB * NH * HID];    // split-s agg partials
__device__ float  g_mid[BB * SLOTS * BD];
__device__ int    g_sidx[BB * SS];
__device__ int    g_cnt[BB];

#define SPART_SZ (BB * NH * SS)
#define APART_SZ (BB * NH * HID)

__device__ __forceinline__ void mma_f16(float* d, const uint32_t* a, const uint32_t* b) {
    asm volatile(
        "mma.sync.aligned.m16n8k16.row.col.f32.f16.f16.f32 "
        "{%0,%1,%2,%3}, {%4,%5,%6,%7}, {%8,%9}, {%0,%1,%2,%3};"
        : "+f"(d[0]), "+f"(d[1]), "+f"(d[2]), "+f"(d[3])
        : "r"(a[0]), "r"(a[1]), "r"(a[2]), "r"(a[3]), "r"(b[0]), "r"(b[1]));
}

__device__ __forceinline__ void cp16(uint32_t smem_dst, const void* gsrc) {
    asm volatile("cp.async.cg.shared.global [%0], [%1], 16;" :: "r"(smem_dst), "l"(gsrc));
}
#define CP_COMMIT asm volatile("cp.async.commit_group;")
#define CP_WAIT2  asm volatile("cp.async.wait_group 2;")
#define CP_WAIT0  asm volatile("cp.async.wait_group 0;")

// ---------------------------------------------------------------------------
// A) HORIZONTAL FUSION: blocks [0,BB) compact+zero g_mid; blocks [BB,..) qproj
__global__ void kA(const int* __restrict__ mask,
                   const float* __restrict__ ms, const float* __restrict__ Wq) {
    int tid = threadIdx.x;
    if (blockIdx.x < BB) {
        __shared__ int tsum[256];
        int b = blockIdx.x;
        const int* m = mask + b * SS;
        int loc[16], cnt = 0;
        #pragma unroll
        for (int k = 0; k < 16; k++) {
            loc[k] = (m[tid * 16 + k] != 0);
            cnt += loc[k];
        }
        tsum[tid] = cnt;
        __syncthreads();
        for (int o = 1; o < 256; o <<= 1) {
            int v = (tid >= o) ? tsum[tid - o] : 0;
            __syncthreads();
            tsum[tid] += v;
            __syncthreads();
        }
        int off = tsum[tid] - cnt;
        int total = tsum[255];
        int* out = g_sidx + b * SS;
        #pragma unroll
        for (int k = 0; k < 16; k++)
            if (loc[k]) out[off++] = tid * 16 + k;
        if (tid == 0) g_cnt[b] = total;
        float* gm = g_mid + b * 4096;
        #pragma unroll
        for (int k = 0; k < 16; k++) gm[k * 256 + tid] = 0.f;
    } else {
        int warp = ((blockIdx.x - BB) * 256 + tid) >> 5;
        int lane = tid & 31;
        if (warp >= SLOTS * BD) return;
        int n = warp / BD, c = warp % BD;
        const float* a = ms + n * HID;
        const float* w = Wq + c * HID;
        float acc = 0.f;
        for (int i = lane; i < HID; i += 32) acc += a[i] * w[i];
        #pragma unroll
        for (int off = 16; off; off >>= 1) acc += __shfl_down_sync(0xffffffffu, acc, off);
        if (lane == 0) g_Q[n * BD + c] = acc;
    }
}

// ---------------------------------------------------------------------------
// B) HORIZONTAL FUSION: blocks [0, BB*SS) conv (1 row/block); rest qk
__global__ void kB(const float* __restrict__ H, const float* __restrict__ Wk) {
    int tid = threadIdx.x;
    int blk = blockIdx.x;
    if (blk < BB * SS) {
        int b = blk >> 12, cs = blk & 4095;
        int cnt = g_cnt[b];
        if (cs < cnt) {
            int s = g_sidx[b * SS + cs];
            const float4* src = (const float4*)(H + ((size_t)b * SS + s) * HID);
            uint2* dst = (uint2*)(g_H16c + ((size_t)b * SS + cs) * HID);
            float4 v0 = src[tid];
            float4 v1 = src[256 + tid];
            float4 v2 = src[512 + tid];
            float4 v3 = src[768 + tid];
            __half2 a0 = __floats2half2_rn(v0.x, v0.y), a1 = __floats2half2_rn(v0.z, v0.w);
            __half2 b0 = __floats2half2_rn(v1.x, v1.y), b1 = __floats2half2_rn(v1.z, v1.w);
            __half2 c0 = __floats2half2_rn(v2.x, v2.y), c1 = __floats2half2_rn(v2.z, v2.w);
            __half2 d0 = __floats2half2_rn(v3.x, v3.y), d1 = __floats2half2_rn(v3.z, v3.w);
            uint2 p0 = make_uint2(*(uint32_t*)&a0, *(uint32_t*)&a1);
            uint2 p1 = make_uint2(*(uint32_t*)&b0, *(uint32_t*)&b1);
            uint2 p2 = make_uint2(*(uint32_t*)&c0, *(uint32_t*)&c1);
            uint2 p3 = make_uint2(*(uint32_t*)&d0, *(uint32_t*)&d1);
            dst[tid] = p0; dst[256 + tid] = p1; dst[512 + tid] = p2; dst[768 + tid] = p3;
        } else if (cs < cnt + 64) {
            uint2* dst = (uint2*)(g_H16c + ((size_t)b * SS + cs) * HID);
            uint2 z = make_uint2(0u, 0u);
            dst[tid] = z; dst[256 + tid] = z; dst[512 + tid] = z; dst[768 + tid] = z;
        }
    } else {
        __shared__ float qs[HD];
        int idx = blk - BB * SS;
        int j = idx >> 4;            // 0..63
        int chunk = idx & 15;
        int h = j >> 3, n = j & 7;
        if (tid < HD) qs[tid] = g_Q[n * BD + h * HD + tid];
        __syncthreads();
        int i = chunk * 256 + tid;
        float acc = 0.f;
        #pragma unroll 8
        for (int d = 0; d < HD; d++) acc += qs[d] * Wk[(h * HD + d) * HID + i];
        g_Qk16[j * HID + i] = __float2half(acc * 0.125f);
    }
}

// ---------------------------------------------------------------------------
// 3) scores fp16: C[cs][j] = H16c[cs,:] . Qk16[j,:], tile 64x64, split-K x4,
//    4-stage cp.async, manual LDS fragments; writes fp16 partials
#define QW 20                      // words per smem tile row (40 halves)
#define SC_TILE_B (64 * QW * 4)    // 5120 B
#define SC_STAGE_B (2 * SC_TILE_B) // 10240 B
__global__ void __launch_bounds__(256) k_scores() {
    extern __shared__ char smc[];
    int b = blockIdx.y, m0 = blockIdx.x * 64, kc = blockIdx.z;
    int cnt = g_cnt[b];
    if (m0 >= cnt) return;
    int tid = threadIdx.x, lane = tid & 31, w = tid >> 5;
    int wm = w & 1, wn = w >> 1;
    int R = wm * 32, C = wn * 16;
    int ar = lane >> 2, ac = lane & 3;
    uint32_t smem_u32 = (uint32_t)__cvta_generic_to_shared(smc);
    const uint32_t* smw = (const uint32_t*)smc;

    float acc[2][2][4];
    #pragma unroll
    for (int t = 0; t < 2; t++)
        #pragma unroll
        for (int n = 0; n < 2; n++)
            #pragma unroll
            for (int q = 0; q < 4; q++) acc[t][n][q] = 0.f;

    int rrow = tid >> 2;
    int rc8 = (tid & 3) * 8;
    const __half* Asrc = g_H16c + ((size_t)b * SS + m0) * HID + kc * 1024;
    const __half* Bsrc = g_Qk16 + kc * 1024;

    auto issue = [&](int stage, int it) {
        int st = it * 32;
        uint32_t base = smem_u32 + stage * SC_STAGE_B;
        cp16(base + rrow * 80 + (tid & 3) * 16, Asrc + (size_t)rrow * HID + st + rc8);
        cp16(base + SC_TILE_B + rrow * 80 + (tid & 3) * 16, Bsrc + (size_t)rrow * HID + st + rc8);
    };

    const int NIT = 32;
    issue(0, 0); CP_COMMIT;
    issue(1, 1); CP_COMMIT;
    issue(2, 2); CP_COMMIT;
    for (int it = 0; it < NIT; it++) {
        CP_WAIT2;
        __syncthreads();
        if (it + 3 < NIT) issue((it + 3) & 3, it + 3);
        CP_COMMIT;
        const uint32_t* As = smw + ((it & 3) * SC_STAGE_B) / 4;
        const uint32_t* Bs = As + SC_TILE_B / 4;
        #pragma unroll
        for (int ks = 0; ks < 2; ks++) {
            int kb = ks * 8;
            uint32_t a[2][4], bf[2][2];
            #pragma unroll
            for (int t = 0; t < 2; t++) {
                int rb = R + t * 16 + ar;
                a[t][0] = As[rb * QW + kb + ac];
                a[t][1] = As[(rb + 8) * QW + kb + ac];
                a[t][2] = As[rb * QW + kb + 4 + ac];
                a[t][3] = As[(rb + 8) * QW + kb + 4 + ac];
            }
            #pragma unroll
            for (int n = 0; n < 2; n++) {
                int cb = C + n * 8 + ar;
                bf[n][0] = Bs[cb * QW + kb + ac];
                bf[n][1] = Bs[cb * QW + kb + 4 + ac];
            }
            #pragma unroll
            for (int t = 0; t < 2; t++)
                #pragma unroll
                for (int n = 0; n < 2; n++)
                    mma_f16(acc[t][n], a[t], bf[n]);
        }
    }
    CP_WAIT0;
    __syncthreads();

    // transpose-stage C (64cs x 64j) -> g_spart16[kc][(b,j)][cs]
    float* Cs = (float*)smc;
    #pragma unroll
    for (int t = 0; t < 2; t++) {
        #pragma unroll
        for (int n = 0; n < 2; n++) {
            int row = R + t * 16 + ar;
            int col = C + n * 8 + 2 * ac;
            Cs[col * 65 + row]            = acc[t][n][0];
            Cs[(col + 1) * 65 + row]      = acc[t][n][1];
            Cs[col * 65 + row + 8]        = acc[t][n][2];
            Cs[(col + 1) * 65 + row + 8]  = acc[t][n][3];
        }
    }
    __syncthreads();
    __half* dst = g_spart16 + (size_t)kc * SPART_SZ;
    #pragma unroll
    for (int l = 0; l < 16; l++) {
        int e = l * 256 + tid;
        int j = e >> 6, m = e & 63;
        dst[((b * NH + j) << 12) + m0 + m] = __float2half(Cs[j * 65 + m]);
    }
}

// ---------------------------------------------------------------------------
// 4) softmax: sum 4 fp16 split-K partials, softmax over compacted prefix
__global__ void k_softmax() {
    __shared__ float red[256];
    int row = blockIdx.x;
    int b = row >> 6;
    int cnt = g_cnt[b];
    const __half* p0 = g_spart16 + (size_t)row * SS;
    __half* sc = g_attnh + (size_t)row * SS;
    int tid = threadIdx.x;
    float v[16];
    float mx = -FLT_MAX;
    #pragma unroll
    for (int k = 0; k < 16; k++) {
        int s = k * 256 + tid;
        float val = -FLT_MAX;
        if (s < cnt)
            val = __half2float(p0[s]) + __half2float(p0[SPART_SZ + s])
                + __half2float(p0[2 * SPART_SZ + s]) + __half2float(p0[3 * SPART_SZ + s]);
        v[k] = val;
        mx = fmaxf(mx, val);
    }
    red[tid] = mx; __syncthreads();
    for (int o = 128; o; o >>= 1) { if (tid < o) red[tid] = fmaxf(red[tid], red[tid + o]); __syncthreads(); }
    mx = red[0]; __syncthreads();
    float sum = 0.f;
    #pragma unroll
    for (int k = 0; k < 16; k++) {
        int s = k * 256 + tid;
        v[k] = (s < cnt) ? __expf(v[k] - mx) : 0.f;
        sum += v[k];
    }
    red[tid] = sum; __syncthreads();
    for (int o = 128; o; o >>= 1) { if (tid < o) red[tid] += red[tid + o]; __syncthreads(); }
    float inv = 1.f / red[0];
    #pragma unroll
    for (int k = 0; k < 16; k++) sc[k * 256 + tid] = __float2half(v[k] * inv);
}

// ---------------------------------------------------------------------------
// 5) agg fp16: tile 64j x 64i, split-s x2, A=attn (manual frags),
//    B=H16c [s][i] via ldmatrix.x4.trans
#define AGA_B (64 * QW * 4)          // 5120 B attn tile
#define AGB_W 36                     // words per H-tile row (72 halves)
#define AGB_B (32 * AGB_W * 4)       // 4608 B
#define AG_STAGE_B (AGA_B + AGB_B)   // 9728 B
__global__ void __launch_bounds__(256) k_agg() {
    extern __shared__ char smc[];
    int tid = threadIdx.x, lane = tid & 31, w = tid >> 5;
    int wm = w & 1, wn = w >> 1;
    int R = wm * 32, C = wn * 16;
    int b = blockIdx.y;
    int i0 = blockIdx.x * 64;
    int sc_id = blockIdx.z;
    int ar = lane >> 2, ac = lane & 3;
    int cnt = g_cnt[b];
    int NIT_total = (cnt + 31) >> 5;
    int half = (NIT_total + 1) >> 1;
    int it0 = sc_id * half;
    int it1 = min(NIT_total, it0 + half);

    uint32_t smem_u32 = (uint32_t)__cvta_generic_to_shared(smc);
    const uint32_t* smw = (const uint32_t*)smc;

    float acc[2][2][4];
    #pragma unroll
    for (int t = 0; t < 2; t++)
        #pragma unroll
        for (int n = 0; n < 2; n++)
            #pragma unroll
            for (int q = 0; q < 4; q++) acc[t][n][q] = 0.f;

    const __half* Asrc = g_attnh + (size_t)b * NH * SS;
    const __half* Bsrc = g_H16c + (size_t)b * SS * HID + i0;

    int rrow = tid >> 2;
    int rc8 = (tid & 3) * 8;
    int brow = tid >> 3;
    int bc8 = (tid & 7) * 8;

    auto issue = [&](int stage, int it) {
        int st = it * 32;
        uint32_t base = smem_u32 + stage * AG_STAGE_B;
        cp16(base + rrow * 80 + (tid & 3) * 16, Asrc + (size_t)rrow * SS + st + rc8);
        cp16(base + AGA_B + brow * 144 + (tid & 7) * 16, Bsrc + (size_t)(st + brow) * HID + bc8);
    };

    int lrow = lane & 15;
    int lcol = C + (lane >> 4) * 8;

    if (it0 < it1) {
        issue(0, it0); CP_COMMIT;
        if (it0 + 1 < it1) issue(1, it0 + 1); CP_COMMIT;
        if (it0 + 2 < it1) issue(2, it0 + 2); CP_COMMIT;
        for (int it = it0; it < it1; it++) {
            CP_WAIT2;
            __syncthreads();
            if (it + 3 < it1) issue((it - it0 + 3) & 3, it + 3);
            CP_COMMIT;
            int stg = (it - it0) & 3;
            const uint32_t* As = smw + (stg * AG_STAGE_B) / 4;
            uint32_t bbase = smem_u32 + stg * AG_STAGE_B + AGA_B;
            #pragma unroll
            for (int ks = 0; ks < 2; ks++) {
                int kb = ks * 8;
                uint32_t a[2][4];
                #pragma unroll
                for (int t = 0; t < 2; t++) {
                    int rb = R + t * 16 + ar;
                    a[t][0] = As[rb * QW + kb + ac];
                    a[t][1] = As[(rb + 8) * QW + kb + ac];
                    a[t][2] = As[rb * QW + kb + 4 + ac];
                    a[t][3] = As[(rb + 8) * QW + kb + 4 + ac];
                }
                uint32_t baddr = bbase + (uint32_t)((ks * 16 + lrow) * 144 + lcol * 2);
                uint32_t rb0, rb1, rb2, rb3;
                asm volatile(
                    "ldmatrix.sync.aligned.m8n8.x4.trans.shared.b16 {%0,%1,%2,%3}, [%4];"
                    : "=r"(rb0), "=r"(rb1), "=r"(rb2), "=r"(rb3) : "r"(baddr));
                uint32_t bf0[2] = {rb0, rb1};
                uint32_t bf1[2] = {rb2, rb3};
                #pragma unroll
                for (int t = 0; t < 2; t++) {
                    mma_f16(acc[t][0], a[t], bf0);
                    mma_f16(acc[t][1], a[t], bf1);
                }
            }
        }
    }

    float* dst = g_apart + sc_id * APART_SZ;
    #pragma unroll
    for (int t = 0; t < 2; t++) {
        #pragma unroll
        for (int n = 0; n < 2; n++) {
            int j = R + t * 16 + ar;
            int i = C + n * 8 + 2 * ac;
            float2 v0 = make_float2(acc[t][n][0], acc[t][n][1]);
            float2 v1 = make_float2(acc[t][n][2], acc[t][n][3]);
            *(float2*)&dst[(size_t)(b * NH + j) * HID + i0 + i]     = v0;
            *(float2*)&dst[(size_t)(b * NH + j + 8) * HID + i0 + i] = v1;
        }
    }
}

// ---------------------------------------------------------------------------
// 6) mid, split-K x4 with atomic epilogue; sums the 2 agg partials
__global__ void k_mid(const float* __restrict__ Wv) {
    __shared__ float As[8][65];
    __shared__ float Bs[64][65];
    int h = blockIdx.x, b = blockIdx.y, kc = blockIdx.z;
    int tid = threadIdx.x;
    float acc0 = 0.f, acc1 = 0.f;
    int o0 = tid, o1 = tid + 256;
    int n0 = o0 >> 6, d0 = o0 & 63;
    int n1 = o1 >> 6, d1 = o1 & 63;
    int k0 = kc * (HID / 4), k1 = k0 + HID / 4;
    for (int kt = k0; kt < k1; kt += 64) {
        {
            int e = tid; int r = e >> 6, c = e & 63;
            size_t ix = (size_t)(b * NH + h * SLOTS + r) * HID + kt + c;
            As[r][c] = g_apart[ix] + g_apart[APART_SZ + ix];
            e = tid + 256; r = e >> 6; c = e & 63;
            ix = (size_t)(b * NH + h * SLOTS + r) * HID + kt + c;
            As[r][c] = g_apart[ix] + g_apart[APART_SZ + ix];
        }
        #pragma unroll
        for (int l = 0; l < 16; l++) {
            int e = tid + l * 256;
            int r = e >> 6, c = e & 63;
            Bs[r][c] = Wv[(h * HD + r) * HID + kt + c];
        }
        __syncthreads();
        #pragma unroll
        for (int k = 0; k < 64; k++) {
            acc0 += As[n0][k] * Bs[d0][k];
            acc1 += As[n1][k] * Bs[d1][k];
        }
        __syncthreads();
    }
    atomicAdd(&g_mid[(b * SLOTS + n0) * BD + h * HD + d0], acc0);
    atomicAdd(&g_mid[(b * SLOTS + n1) * BD + h * HD + d1], acc1);
}

// ---------------------------------------------------------------------------
// 7) final, o-tile 64
__global__ void k_final(const float* __restrict__ Wo, float* __restrict__ out) {
    __shared__ float As[32][65];
    __shared__ float Bs[64][65];
    int tid = threadIdx.x;
    int tx = tid & 15, ty = tid >> 4;
    int o0 = blockIdx.x * 64;
    float acc[2][4] = {};
    for (int kt = 0; kt < BD; kt += 64) {
        #pragma unroll
        for (int l = 0; l < 8; l++) {
            int e = tid + l * 256;
            int r = e >> 6, c = e & 63;
            As[r][c] = g_mid[r * BD + kt + c];
        }
        #pragma unroll
        for (int l = 0; l < 16; l++) {
            int e = tid + l * 256;
            int r = e >> 6, c = e & 63;
            Bs[r][c] = Wo[(o0 + r) * BD + kt + c];
        }
        __syncthreads();
        #pragma unroll
        for (int k = 0; k < 64; k++) {
            float a[2], bb[4];
            #pragma unroll
            for (int x = 0; x < 2; x++) a[x] = As[ty * 2 + x][k];
            #pragma unroll
            for (int y = 0; y < 4; y++) bb[y] = Bs[tx * 4 + y][k];
            #pragma unroll
            for (int x = 0; x < 2; x++)
                #pragma unroll
                for (int y = 0; y < 4; y++) acc[x][y] += a[x] * bb[y];
        }
        __syncthreads();
    }
    #pragma unroll
    for (int x = 0; x < 2; x++)
        #pragma unroll
        for (int y = 0; y < 4; y++)
            out[(ty * 2 + x) * HID + o0 + tx * 4 + y] = acc[x][y];
}

// ---------------------------------------------------------------------------
extern "C" void kernel_launch(void* const* d_in, const int* in_sizes, int n_in,
                              void* d_out, int out_size) {
    const float* H    = (const float*)d_in[0];
    const int*   mask = (const int*)d_in[1];
    const float* ms   = (const float*)d_in[2];
    const float* Wq   = (const float*)d_in[3];
    const float* Wk   = (const float*)d_in[4];
    const float* Wv   = (const float*)d_in[5];
    const float* Wo   = (const float*)d_in[6];
    float* out = (float*)d_out;

    kA<<<BB + 512, 256>>>(mask, ms, Wq);
    kB<<<BB * SS + NH * 16, 256>>>(H, Wk);
    k_scores<<<dim3(SS / 64, BB, 4), 256, 4 * SC_STAGE_B>>>();
    k_softmax<<<BB * NH, 256>>>();
    k_agg   <<<dim3(HID / 64, BB, 2), 256, 4 * AG_STAGE_B>>>();
    k_mid   <<<dim3(HEADS, BB, 4), 256>>>(Wv);
    k_final <<<HID / 64, 256>>>(Wo, out);
}

// round 12
// speedup vs baseline: 1.2037x; 1.0326x over previous
#include <cuda_runtime.h>
#include <cuda_fp16.h>
#include <float.h>
#include <stdint.h>

#define HID 4096
#define SLOTS 8
#define HEADS 8
#define BD 512
#define HD 64
#define BB 4
#define SS 4096
#define NH 64   // HEADS*SLOTS

// Scratch (no allocations allowed)
__device__ float  g_Q[SLOTS * BD];
__device__ __half g_Qk16[NH * HID];              // fp16, scaled by 1/8
__device__ __half g_H16c[(size_t)BB * SS * HID]; // fp16 H, compacted rows
__device__ __half g_spart16[4 * BB * NH * SS];   // split-K score partials (fp16)
__device__ __half g_attnh[BB * NH * SS];         // attn probs (fp16)
__device__ float  g_apart[2 * BB * NH * HID];    // split-s agg partials
__device__ float  g_mid[BB * SLOTS * BD];
__device__ int    g_sidx[BB * SS];
__device__ int    g_cnt[BB];

#define SPART_SZ (BB * NH * SS)
#define APART_SZ (BB * NH * HID)

__device__ __forceinline__ void mma_f16(float* d, const uint32_t* a, const uint32_t* b) {
    asm volatile(
        "mma.sync.aligned.m16n8k16.row.col.f32.f16.f16.f32 "
        "{%0,%1,%2,%3}, {%4,%5,%6,%7}, {%8,%9}, {%0,%1,%2,%3};"
        : "+f"(d[0]), "+f"(d[1]), "+f"(d[2]), "+f"(d[3])
        : "r"(a[0]), "r"(a[1]), "r"(a[2]), "r"(a[3]), "r"(b[0]), "r"(b[1]));
}

__device__ __forceinline__ void ldm_x4(uint32_t* r, uint32_t addr) {
    asm volatile(
        "ldmatrix.sync.aligned.m8n8.x4.shared.b16 {%0,%1,%2,%3}, [%4];"
        : "=r"(r[0]), "=r"(r[1]), "=r"(r[2]), "=r"(r[3]) : "r"(addr));
}

__device__ __forceinline__ void cp16(uint32_t smem_dst, const void* gsrc) {
    asm volatile("cp.async.cg.shared.global [%0], [%1], 16;" :: "r"(smem_dst), "l"(gsrc));
}
#define CP_COMMIT asm volatile("cp.async.commit_group;")
#define CP_WAIT2  asm volatile("cp.async.wait_group 2;")
#define CP_WAIT0  asm volatile("cp.async.wait_group 0;")

// ---------------------------------------------------------------------------
// A) HORIZONTAL FUSION: blocks [0,BB) compact+zero g_mid; blocks [BB,..) qproj
__global__ void kA(const int* __restrict__ mask,
                   const float* __restrict__ ms, const float* __restrict__ Wq) {
    int tid = threadIdx.x;
    if (blockIdx.x < BB) {
        __shared__ int tsum[256];
        int b = blockIdx.x;
        const int* m = mask + b * SS;
        int loc[16], cnt = 0;
        #pragma unroll
        for (int k = 0; k < 16; k++) {
            loc[k] = (m[tid * 16 + k] != 0);
            cnt += loc[k];
        }
        tsum[tid] = cnt;
        __syncthreads();
        for (int o = 1; o < 256; o <<= 1) {
            int v = (tid >= o) ? tsum[tid - o] : 0;
            __syncthreads();
            tsum[tid] += v;
            __syncthreads();
        }
        int off = tsum[tid] - cnt;
        int total = tsum[255];
        int* out = g_sidx + b * SS;
        #pragma unroll
        for (int k = 0; k < 16; k++)
            if (loc[k]) out[off++] = tid * 16 + k;
        if (tid == 0) g_cnt[b] = total;
        float* gm = g_mid + b * 4096;
        #pragma unroll
        for (int k = 0; k < 16; k++) gm[k * 256 + tid] = 0.f;
    } else {
        int warp = ((blockIdx.x - BB) * 256 + tid) >> 5;
        int lane = tid & 31;
        if (warp >= SLOTS * BD) return;
        int n = warp / BD, c = warp % BD;
        const float* a = ms + n * HID;
        const float* w = Wq + c * HID;
        float acc = 0.f;
        for (int i = lane; i < HID; i += 32) acc += a[i] * w[i];
        #pragma unroll
        for (int off = 16; off; off >>= 1) acc += __shfl_down_sync(0xffffffffu, acc, off);
        if (lane == 0) g_Q[n * BD + c] = acc;
    }
}

// ---------------------------------------------------------------------------
// B) HORIZONTAL FUSION: blocks [0, BB*SS) conv (1 row/block); rest qk
__global__ void kB(const float* __restrict__ H, const float* __restrict__ Wk) {
    int tid = threadIdx.x;
    int blk = blockIdx.x;
    if (blk < BB * SS) {
        int b = blk >> 12, cs = blk & 4095;
        int cnt = g_cnt[b];
        if (cs < cnt) {
            int s = g_sidx[b * SS + cs];
            const float4* src = (const float4*)(H + ((size_t)b * SS + s) * HID);
            uint2* dst = (uint2*)(g_H16c + ((size_t)b * SS + cs) * HID);
            float4 v0 = src[tid];
            float4 v1 = src[256 + tid];
            float4 v2 = src[512 + tid];
            float4 v3 = src[768 + tid];
            __half2 a0 = __floats2half2_rn(v0.x, v0.y), a1 = __floats2half2_rn(v0.z, v0.w);
            __half2 b0 = __floats2half2_rn(v1.x, v1.y), b1 = __floats2half2_rn(v1.z, v1.w);
            __half2 c0 = __floats2half2_rn(v2.x, v2.y), c1 = __floats2half2_rn(v2.z, v2.w);
            __half2 d0 = __floats2half2_rn(v3.x, v3.y), d1 = __floats2half2_rn(v3.z, v3.w);
            uint2 p0 = make_uint2(*(uint32_t*)&a0, *(uint32_t*)&a1);
            uint2 p1 = make_uint2(*(uint32_t*)&b0, *(uint32_t*)&b1);
            uint2 p2 = make_uint2(*(uint32_t*)&c0, *(uint32_t*)&c1);
            uint2 p3 = make_uint2(*(uint32_t*)&d0, *(uint32_t*)&d1);
            dst[tid] = p0; dst[256 + tid] = p1; dst[512 + tid] = p2; dst[768 + tid] = p3;
        } else if (cs < cnt + 64) {
            uint2* dst = (uint2*)(g_H16c + ((size_t)b * SS + cs) * HID);
            uint2 z = make_uint2(0u, 0u);
            dst[tid] = z; dst[256 + tid] = z; dst[512 + tid] = z; dst[768 + tid] = z;
        }
    } else {
        __shared__ float qs[HD];
        int idx = blk - BB * SS;
        int j = idx >> 4;            // 0..63
        int chunk = idx & 15;
        int h = j >> 3, n = j & 7;
        if (tid < HD) qs[tid] = g_Q[n * BD + h * HD + tid];
        __syncthreads();
        int i = chunk * 256 + tid;
        float acc = 0.f;
        #pragma unroll 8
        for (int d = 0; d < HD; d++) acc += qs[d] * Wk[(h * HD + d) * HID + i];
        g_Qk16[j * HID + i] = __float2half(acc * 0.125f);
    }
}

// ---------------------------------------------------------------------------
// 3) scores fp16: C[cs][j] = H16c[cs,:] . Qk16[j,:], tile 64x64, split-K x4,
//    4-stage cp.async, ldmatrix fragments
#define QW 20                      // words per smem tile row (40 halves)
#define SC_TILE_B (64 * QW * 4)    // 5120 B
#define SC_STAGE_B (2 * SC_TILE_B) // 10240 B
__global__ void __launch_bounds__(256) k_scores() {
    extern __shared__ char smc[];
    int b = blockIdx.y, m0 = blockIdx.x * 64, kc = blockIdx.z;
    int cnt = g_cnt[b];
    if (m0 >= cnt) return;
    int tid = threadIdx.x, lane = tid & 31, w = tid >> 5;
    int wm = w & 1, wn = w >> 1;
    int R = wm * 32, C = wn * 16;
    int ar = lane >> 2, ac = lane & 3;
    uint32_t smem_u32 = (uint32_t)__cvta_generic_to_shared(smc);

    float acc[2][2][4];
    #pragma unroll
    for (int t = 0; t < 2; t++)
        #pragma unroll
        for (int n = 0; n < 2; n++)
            #pragma unroll
            for (int q = 0; q < 4; q++) acc[t][n][q] = 0.f;

    int rrow = tid >> 2;
    int rc8 = (tid & 3) * 8;
    const __half* Asrc = g_H16c + ((size_t)b * SS + m0) * HID + kc * 1024;
    const __half* Bsrc = g_Qk16 + kc * 1024;

    auto issue = [&](int stage, int it) {
        int st = it * 32;
        uint32_t base = smem_u32 + stage * SC_STAGE_B;
        cp16(base + rrow * 80 + (tid & 3) * 16, Asrc + (size_t)rrow * HID + st + rc8);
        cp16(base + SC_TILE_B + rrow * 80 + (tid & 3) * 16, Bsrc + (size_t)rrow * HID + st + rc8);
    };

    int lr16 = lane & 15;
    int lhi = lane >> 4;

    const int NIT = 32;
    issue(0, 0); CP_COMMIT;
    issue(1, 1); CP_COMMIT;
    issue(2, 2); CP_COMMIT;
    for (int it = 0; it < NIT; it++) {
        CP_WAIT2;
        __syncthreads();
        if (it + 3 < NIT) issue((it + 3) & 3, it + 3);
        CP_COMMIT;
        uint32_t abase = smem_u32 + (it & 3) * SC_STAGE_B;
        uint32_t bbase = abase + SC_TILE_B;
        #pragma unroll
        for (int ks = 0; ks < 2; ks++) {
            uint32_t colb = (uint32_t)(ks * 32 + lhi * 16);
            uint32_t a[2][4];
            #pragma unroll
            for (int t = 0; t < 2; t++)
                ldm_x4(a[t], abase + (uint32_t)((R + t * 16 + lr16) * 80) + colb);
            uint32_t rb[4];
            ldm_x4(rb, bbase + (uint32_t)((C + lr16) * 80) + colb);
            uint32_t bf0[2] = {rb[0], rb[2]};
            uint32_t bf1[2] = {rb[1], rb[3]};
            #pragma unroll
            for (int t = 0; t < 2; t++) {
                mma_f16(acc[t][0], a[t], bf0);
                mma_f16(acc[t][1], a[t], bf1);
            }
        }
    }
    CP_WAIT0;
    __syncthreads();

    // transpose-stage C (64cs x 64j) -> g_spart16[kc][(b,j)][cs]
    float* Cs = (float*)smc;
    #pragma unroll
    for (int t = 0; t < 2; t++) {
        #pragma unroll
        for (int n = 0; n < 2; n++) {
            int row = R + t * 16 + ar;
            int col = C + n * 8 + 2 * ac;
            Cs[col * 65 + row]            = acc[t][n][0];
            Cs[(col + 1) * 65 + row]      = acc[t][n][1];
            Cs[col * 65 + row + 8]        = acc[t][n][2];
            Cs[(col + 1) * 65 + row + 8]  = acc[t][n][3];
        }
    }
    __syncthreads();
    __half* dst = g_spart16 + (size_t)kc * SPART_SZ;
    #pragma unroll
    for (int l = 0; l < 16; l++) {
        int e = l * 256 + tid;
        int j = e >> 6, m = e & 63;
        dst[((b * NH + j) << 12) + m0 + m] = __float2half(Cs[j * 65 + m]);
    }
}

// ---------------------------------------------------------------------------
// 4) softmax: sum 4 fp16 split-K partials, softmax over compacted prefix
__global__ void k_softmax() {
    __shared__ float red[256];
    int row = blockIdx.x;
    int b = row >> 6;
    int cnt = g_cnt[b];
    const __half* p0 = g_spart16 + (size_t)row * SS;
    __half* sc = g_attnh + (size_t)row * SS;
    int tid = threadIdx.x;
    float v[16];
    float mx = -FLT_MAX;
    #pragma unroll
    for (int k = 0; k < 16; k++) {
        int s = k * 256 + tid;
        float val = -FLT_MAX;
        if (s < cnt)
            val = __half2float(p0[s]) + __half2float(p0[SPART_SZ + s])
                + __half2float(p0[2 * SPART_SZ + s]) + __half2float(p0[3 * SPART_SZ + s]);
        v[k] = val;
        mx = fmaxf(mx, val);
    }
    red[tid] = mx; __syncthreads();
    for (int o = 128; o; o >>= 1) { if (tid < o) red[tid] = fmaxf(red[tid], red[tid + o]); __syncthreads(); }
    mx = red[0]; __syncthreads();
    float sum = 0.f;
    #pragma unroll
    for (int k = 0; k < 16; k++) {
        int s = k * 256 + tid;
        v[k] = (s < cnt) ? __expf(v[k] - mx) : 0.f;
        sum += v[k];
    }
    red[tid] = sum; __syncthreads();
    for (int o = 128; o; o >>= 1) { if (tid < o) red[tid] += red[tid + o]; __syncthreads(); }
    float inv = 1.f / red[0];
    #pragma unroll
    for (int k = 0; k < 16; k++) sc[k * 256 + tid] = __float2half(v[k] * inv);
}

// ---------------------------------------------------------------------------
// 5) agg fp16: tile 64j x 64i, split-s x2, A via ldmatrix.x4,
//    B=H16c [s][i] via ldmatrix.x4.trans
#define AGA_B (64 * QW * 4)          // 5120 B attn tile
#define AGB_W 36                     // words per H-tile row (72 halves)
#define AGB_B (32 * AGB_W * 4)       // 4608 B
#define AG_STAGE_B (AGA_B + AGB_B)   // 9728 B
__global__ void __launch_bounds__(256) k_agg() {
    extern __shared__ char smc[];
    int tid = threadIdx.x, lane = tid & 31, w = tid >> 5;
    int wm = w & 1, wn = w >> 1;
    int R = wm * 32, C = wn * 16;
    int b = blockIdx.y;
    int i0 = blockIdx.x * 64;
    int sc_id = blockIdx.z;
    int ar = lane >> 2, ac = lane & 3;
    int cnt = g_cnt[b];
    int NIT_total = (cnt + 31) >> 5;
    int half = (NIT_total + 1) >> 1;
    int it0 = sc_id * half;
    int it1 = min(NIT_total, it0 + half);

    uint32_t smem_u32 = (uint32_t)__cvta_generic_to_shared(smc);

    float acc[2][2][4];
    #pragma unroll
    for (int t = 0; t < 2; t++)
        #pragma unroll
        for (int n = 0; n < 2; n++)
            #pragma unroll
            for (int q = 0; q < 4; q++) acc[t][n][q] = 0.f;

    const __half* Asrc = g_attnh + (size_t)b * NH * SS;
    const __half* Bsrc = g_H16c + (size_t)b * SS * HID + i0;

    int rrow = tid >> 2;
    int rc8 = (tid & 3) * 8;
    int brow = tid >> 3;
    int bc8 = (tid & 7) * 8;

    auto issue = [&](int stage, int it) {
        int st = it * 32;
        uint32_t base = smem_u32 + stage * AG_STAGE_B;
        cp16(base + rrow * 80 + (tid & 3) * 16, Asrc + (size_t)rrow * SS + st + rc8);
        cp16(base + AGA_B + brow * 144 + (tid & 7) * 16, Bsrc + (size_t)(st + brow) * HID + bc8);
    };

    int lr16 = lane & 15;
    int lhi = lane >> 4;
    int lrow = lane & 15;
    int lcol = C + (lane >> 4) * 8;

    if (it0 < it1) {
        issue(0, it0); CP_COMMIT;
        if (it0 + 1 < it1) issue(1, it0 + 1); CP_COMMIT;
        if (it0 + 2 < it1) issue(2, it0 + 2); CP_COMMIT;
        for (int it = it0; it < it1; it++) {
            CP_WAIT2;
            __syncthreads();
            if (it + 3 < it1) issue((it - it0 + 3) & 3, it + 3);
            CP_COMMIT;
            int stg = (it - it0) & 3;
            uint32_t abase = smem_u32 + stg * AG_STAGE_B;
            uint32_t bbase = abase + AGA_B;
            #pragma unroll
            for (int ks = 0; ks < 2; ks++) {
                uint32_t colb = (uint32_t)(ks * 32 + lhi * 16);
                uint32_t a[2][4];
                #pragma unroll
                for (int t = 0; t < 2; t++)
                    ldm_x4(a[t], abase + (uint32_t)((R + t * 16 + lr16) * 80) + colb);
                uint32_t baddr = bbase + (uint32_t)((ks * 16 + lrow) * 144 + lcol * 2);
                uint32_t rb0, rb1, rb2, rb3;
                asm volatile(
                    "ldmatrix.sync.aligned.m8n8.x4.trans.shared.b16 {%0,%1,%2,%3}, [%4];"
                    : "=r"(rb0), "=r"(rb1), "=r"(rb2), "=r"(rb3) : "r"(baddr));
                uint32_t bf0[2] = {rb0, rb1};
                uint32_t bf1[2] = {rb2, rb3};
                #pragma unroll
                for (int t = 0; t < 2; t++) {
                    mma_f16(acc[t][0], a[t], bf0);
                    mma_f16(acc[t][1], a[t], bf1);
                }
            }
        }
    }

    float* dst = g_apart + sc_id * APART_SZ;
    #pragma unroll
    for (int t = 0; t < 2; t++) {
        #pragma unroll
        for (int n = 0; n < 2; n++) {
            int j = R + t * 16 + ar;
            int i = C + n * 8 + 2 * ac;
            float2 v0 = make_float2(acc[t][n][0], acc[t][n][1]);
            float2 v1 = make_float2(acc[t][n][2], acc[t][n][3]);
            *(float2*)&dst[(size_t)(b * NH + j) * HID + i0 + i]     = v0;
            *(float2*)&dst[(size_t)(b * NH + j + 8) * HID + i0 + i] = v1;
        }
    }
}

// ---------------------------------------------------------------------------
// 6) mid, split-K x4 with atomic epilogue; sums the 2 agg partials
__global__ void k_mid(const float* __restrict__ Wv) {
    __shared__ float As[8][65];
    __shared__ float Bs[64][65];
    int h = blockIdx.x, b = blockIdx.y, kc = blockIdx.z;
    int tid = threadIdx.x;
    float acc0 = 0.f, acc1 = 0.f;
    int o0 = tid, o1 = tid + 256;
    int n0 = o0 >> 6, d0 = o0 & 63;
    int n1 = o1 >> 6, d1 = o1 & 63;
    int k0 = kc * (HID / 4), k1 = k0 + HID / 4;
    for (int kt = k0; kt < k1; kt += 64) {
        {
            int e = tid; int r = e >> 6, c = e & 63;
            size_t ix = (size_t)(b * NH + h * SLOTS + r) * HID + kt + c;
            As[r][c] = g_apart[ix] + g_apart[APART_SZ + ix];
            e = tid + 256; r = e >> 6; c = e & 63;
            ix = (size_t)(b * NH + h * SLOTS + r) * HID + kt + c;
            As[r][c] = g_apart[ix] + g_apart[APART_SZ + ix];
        }
        #pragma unroll
        for (int l = 0; l < 16; l++) {
            int e = tid + l * 256;
            int r = e >> 6, c = e & 63;
            Bs[r][c] = Wv[(h * HD + r) * HID + kt + c];
        }
        __syncthreads();
        #pragma unroll
        for (int k = 0; k < 64; k++) {
            acc0 += As[n0][k] * Bs[d0][k];
            acc1 += As[n1][k] * Bs[d1][k];
        }
        __syncthreads();
    }
    atomicAdd(&g_mid[(b * SLOTS + n0) * BD + h * HD + d0], acc0);
    atomicAdd(&g_mid[(b * SLOTS + n1) * BD + h * HD + d1], acc1);
}

// ---------------------------------------------------------------------------
// 7) final, o-tile 64
__global__ void k_final(const float* __restrict__ Wo, float* __restrict__ out) {
    __shared__ float As[32][65];
    __shared__ float Bs[64][65];
    int tid = threadIdx.x;
    int tx = tid & 15, ty = tid >> 4;
    int o0 = blockIdx.x * 64;
    float acc[2][4] = {};
    for (int kt = 0; kt < BD; kt += 64) {
        #pragma unroll
        for (int l = 0; l < 8; l++) {
            int e = tid + l * 256;
            int r = e >> 6, c = e & 63;
            As[r][c] = g_mid[r * BD + kt + c];
        }
        #pragma unroll
        for (int l = 0; l < 16; l++) {
            int e = tid + l * 256;
            int r = e >> 6, c = e & 63;
            Bs[r][c] = Wo[(o0 + r) * BD + kt + c];
        }
        __syncthreads();
        #pragma unroll
        for (int k = 0; k < 64; k++) {
            float a[2], bb[4];
            #pragma unroll
            for (int x = 0; x < 2; x++) a[x] = As[ty * 2 + x][k];
            #pragma unroll
            for (int y = 0; y < 4; y++) bb[y] = Bs[tx * 4 + y][k];
            #pragma unroll
            for (int x = 0; x < 2; x++)
                #pragma unroll
                for (int y = 0; y < 4; y++) acc[x][y] += a[x] * bb[y];
        }
        __syncthreads();
    }
    #pragma unroll
    for (int x = 0; x < 2; x++)
        #pragma unroll
        for (int y = 0; y < 4; y++)
            out[(ty * 2 + x) * HID + o0 + tx * 4 + y] = acc[x][y];
}

// ---------------------------------------------------------------------------
extern "C" void kernel_launch(void* const* d_in, const int* in_sizes, int n_in,
                              void* d_out, int out_size) {
    const float* H    = (const float*)d_in[0];
    const int*   mask = (const int*)d_in[1];
    const float* ms   = (const float*)d_in[2];
    const float* Wq   = (const float*)d_in[3];
    const float* Wk   = (const float*)d_in[4];
    const float* Wv   = (const float*)d_in[5];
    const float* Wo   = (const float*)d_in[6];
    float* out = (float*)d_out;

    kA<<<BB + 512, 256>>>(mask, ms, Wq);
    kB<<<BB * SS + NH * 16, 256>>>(H, Wk);
    k_scores<<<dim3(SS / 64, BB, 4), 256, 4 * SC_STAGE_B>>>();
    k_softmax<<<BB * NH, 256>>>();
    k_agg   <<<dim3(HID / 64, BB, 2), 256, 4 * AG_STAGE_B>>>();
    k_mid   <<<dim3(HEADS, BB, 4), 256>>>(Wv);
    k_final <<<HID / 64, 256>>>(Wo, out);
}

// round 13
// speedup vs baseline: 1.2425x; 1.0322x over previous
#include <cuda_runtime.h>
#include <cuda_fp16.h>
#include <float.h>
#include <stdint.h>

#define HID 4096
#define SLOTS 8
#define HEADS 8
#define BD 512
#define HD 64
#define BB 4
#define SS 4096
#define NH 64   // HEADS*SLOTS

// Scratch (no allocations allowed)
__device__ float  g_Q[SLOTS * BD];
__device__ __half g_Qk16[NH * HID];              // fp16, scaled by 1/8
__device__ __half g_H16c[(size_t)BB * SS * HID]; // fp16 H, compacted rows
__device__ __half g_spart16[4 * BB * NH * SS];   // split-K score partials (fp16)
__device__ __half g_attnh[BB * NH * SS];         // attn probs (fp16)
__device__ float  g_apart[2 * BB * NH * HID];    // split-s agg partials
__device__ float  g_mid[BB * SLOTS * BD];
__device__ int    g_sidx[BB * SS];
__device__ int    g_cnt[BB];

#define SPART_SZ (BB * NH * SS)
#define APART_SZ (BB * NH * HID)

__device__ __forceinline__ void mma_f16(float* d, const uint32_t* a, const uint32_t* b) {
    asm volatile(
        "mma.sync.aligned.m16n8k16.row.col.f32.f16.f16.f32 "
        "{%0,%1,%2,%3}, {%4,%5,%6,%7}, {%8,%9}, {%0,%1,%2,%3};"
        : "+f"(d[0]), "+f"(d[1]), "+f"(d[2]), "+f"(d[3])
        : "r"(a[0]), "r"(a[1]), "r"(a[2]), "r"(a[3]), "r"(b[0]), "r"(b[1]));
}

__device__ __forceinline__ void ldm_x4(uint32_t* r, uint32_t addr) {
    asm volatile(
        "ldmatrix.sync.aligned.m8n8.x4.shared.b16 {%0,%1,%2,%3}, [%4];"
        : "=r"(r[0]), "=r"(r[1]), "=r"(r[2]), "=r"(r[3]) : "r"(addr));
}

__device__ __forceinline__ void ldm_x4t(uint32_t* r, uint32_t addr) {
    asm volatile(
        "ldmatrix.sync.aligned.m8n8.x4.trans.shared.b16 {%0,%1,%2,%3}, [%4];"
        : "=r"(r[0]), "=r"(r[1]), "=r"(r[2]), "=r"(r[3]) : "r"(addr));
}

__device__ __forceinline__ void cp16(uint32_t smem_dst, const void* gsrc) {
    asm volatile("cp.async.cg.shared.global [%0], [%1], 16;" :: "r"(smem_dst), "l"(gsrc));
}
#define CP_COMMIT asm volatile("cp.async.commit_group;")
#define CP_WAIT2  asm volatile("cp.async.wait_group 2;")
#define CP_WAIT0  asm volatile("cp.async.wait_group 0;")

// ---------------------------------------------------------------------------
// A) HORIZONTAL FUSION: blocks [0,BB) compact+zero g_mid; blocks [BB,..) qproj
__global__ void kA(const int* __restrict__ mask,
                   const float* __restrict__ ms, const float* __restrict__ Wq) {
    int tid = threadIdx.x;
    if (blockIdx.x < BB) {
        __shared__ int tsum[256];
        int b = blockIdx.x;
        const int* m = mask + b * SS;
        int loc[16], cnt = 0;
        #pragma unroll
        for (int k = 0; k < 16; k++) {
            loc[k] = (m[tid * 16 + k] != 0);
            cnt += loc[k];
        }
        tsum[tid] = cnt;
        __syncthreads();
        for (int o = 1; o < 256; o <<= 1) {
            int v = (tid >= o) ? tsum[tid - o] : 0;
            __syncthreads();
            tsum[tid] += v;
            __syncthreads();
        }
        int off = tsum[tid] - cnt;
        int total = tsum[255];
        int* out = g_sidx + b * SS;
        #pragma unroll
        for (int k = 0; k < 16; k++)
            if (loc[k]) out[off++] = tid * 16 + k;
        if (tid == 0) g_cnt[b] = total;
        float* gm = g_mid + b * 4096;
        #pragma unroll
        for (int k = 0; k < 16; k++) gm[k * 256 + tid] = 0.f;
    } else {
        int warp = ((blockIdx.x - BB) * 256 + tid) >> 5;
        int lane = tid & 31;
        if (warp >= SLOTS * BD) return;
        int n = warp / BD, c = warp % BD;
        const float* a = ms + n * HID;
        const float* w = Wq + c * HID;
        float acc = 0.f;
        for (int i = lane; i < HID; i += 32) acc += a[i] * w[i];
        #pragma unroll
        for (int off = 16; off; off >>= 1) acc += __shfl_down_sync(0xffffffffu, acc, off);
        if (lane == 0) g_Q[n * BD + c] = acc;
    }
}

// ---------------------------------------------------------------------------
// B) HORIZONTAL FUSION: blocks [0, BB*SS) conv (1 row/block, pad 128); rest qk
__global__ void kB(const float* __restrict__ H, const float* __restrict__ Wk) {
    int tid = threadIdx.x;
    int blk = blockIdx.x;
    if (blk < BB * SS) {
        int b = blk >> 12, cs = blk & 4095;
        int cnt = g_cnt[b];
        if (cs < cnt) {
            int s = g_sidx[b * SS + cs];
            const float4* src = (const float4*)(H + ((size_t)b * SS + s) * HID);
            uint2* dst = (uint2*)(g_H16c + ((size_t)b * SS + cs) * HID);
            float4 v0 = src[tid];
            float4 v1 = src[256 + tid];
            float4 v2 = src[512 + tid];
            float4 v3 = src[768 + tid];
            __half2 a0 = __floats2half2_rn(v0.x, v0.y), a1 = __floats2half2_rn(v0.z, v0.w);
            __half2 b0 = __floats2half2_rn(v1.x, v1.y), b1 = __floats2half2_rn(v1.z, v1.w);
            __half2 c0 = __floats2half2_rn(v2.x, v2.y), c1 = __floats2half2_rn(v2.z, v2.w);
            __half2 d0 = __floats2half2_rn(v3.x, v3.y), d1 = __floats2half2_rn(v3.z, v3.w);
            uint2 p0 = make_uint2(*(uint32_t*)&a0, *(uint32_t*)&a1);
            uint2 p1 = make_uint2(*(uint32_t*)&b0, *(uint32_t*)&b1);
            uint2 p2 = make_uint2(*(uint32_t*)&c0, *(uint32_t*)&c1);
            uint2 p3 = make_uint2(*(uint32_t*)&d0, *(uint32_t*)&d1);
            dst[tid] = p0; dst[256 + tid] = p1; dst[512 + tid] = p2; dst[768 + tid] = p3;
        } else if (cs < cnt + 128) {
            uint2* dst = (uint2*)(g_H16c + ((size_t)b * SS + cs) * HID);
            uint2 z = make_uint2(0u, 0u);
            dst[tid] = z; dst[256 + tid] = z; dst[512 + tid] = z; dst[768 + tid] = z;
        }
    } else {
        __shared__ float qs[HD];
        int idx = blk - BB * SS;
        int j = idx >> 4;            // 0..63
        int chunk = idx & 15;
        int h = j >> 3, n = j & 7;
        if (tid < HD) qs[tid] = g_Q[n * BD + h * HD + tid];
        __syncthreads();
        int i = chunk * 256 + tid;
        float acc = 0.f;
        #pragma unroll 8
        for (int d = 0; d < HD; d++) acc += qs[d] * Wk[(h * HD + d) * HID + i];
        g_Qk16[j * HID + i] = __float2half(acc * 0.125f);
    }
}

// ---------------------------------------------------------------------------
// 3) scores fp16: tile 128cs x 64j, split-K x4, 4-stage cp.async, ldmatrix
#define SC_A_B (128 * 80)           // 10240 B
#define SC_B_B (64 * 80)            // 5120 B
#define SC_STAGE_B (SC_A_B + SC_B_B)// 15360 B
__global__ void __launch_bounds__(256) k_scores() {
    extern __shared__ char smc[];
    int b = blockIdx.y, m0 = blockIdx.x * 128, kc = blockIdx.z;
    int cnt = g_cnt[b];
    if (m0 >= cnt) return;
    int tid = threadIdx.x, lane = tid & 31, w = tid >> 5;
    int wm = w & 3, wn = w >> 2;       // 4 m-groups x 2 n-groups
    int R = wm * 32, C = wn * 32;
    int ar = lane >> 2, ac = lane & 3;
    uint32_t smem_u32 = (uint32_t)__cvta_generic_to_shared(smc);

    float acc[2][4][4];
    #pragma unroll
    for (int t = 0; t < 2; t++)
        #pragma unroll
        for (int n = 0; n < 4; n++)
            #pragma unroll
            for (int q = 0; q < 4; q++) acc[t][n][q] = 0.f;

    int arow = tid >> 2;               // 0..63
    int aseg = tid & 3;                // 0..3 x16B
    const __half* Asrc = g_H16c + ((size_t)b * SS + m0) * HID + kc * 1024;
    const __half* Bsrc = g_Qk16 + kc * 1024;

    auto issue = [&](int stage, int it) {
        int st = it * 32;
        uint32_t base = smem_u32 + stage * SC_STAGE_B;
        cp16(base + arow * 80 + aseg * 16, Asrc + (size_t)arow * HID + st + aseg * 8);
        cp16(base + (arow + 64) * 80 + aseg * 16,
             Asrc + (size_t)(arow + 64) * HID + st + aseg * 8);
        cp16(base + SC_A_B + arow * 80 + aseg * 16,
             Bsrc + (size_t)arow * HID + st + aseg * 8);
    };

    int lr16 = lane & 15;
    int lhi = lane >> 4;

    const int NIT = 32;
    issue(0, 0); CP_COMMIT;
    issue(1, 1); CP_COMMIT;
    issue(2, 2); CP_COMMIT;
    for (int it = 0; it < NIT; it++) {
        CP_WAIT2;
        __syncthreads();
        if (it + 3 < NIT) issue((it + 3) & 3, it + 3);
        CP_COMMIT;
        uint32_t abase = smem_u32 + (it & 3) * SC_STAGE_B;
        uint32_t bbase = abase + SC_A_B;
        #pragma unroll
        for (int ks = 0; ks < 2; ks++) {
            uint32_t colb = (uint32_t)(ks * 32 + lhi * 16);
            uint32_t a[2][4];
            #pragma unroll
            for (int t = 0; t < 2; t++)
                ldm_x4(a[t], abase + (uint32_t)((R + t * 16 + lr16) * 80) + colb);
            uint32_t rbA[4], rbB[4];
            ldm_x4(rbA, bbase + (uint32_t)((C + lr16) * 80) + colb);
            ldm_x4(rbB, bbase + (uint32_t)((C + 16 + lr16) * 80) + colb);
            uint32_t bf[4][2] = {{rbA[0], rbA[2]}, {rbA[1], rbA[3]},
                                 {rbB[0], rbB[2]}, {rbB[1], rbB[3]}};
            #pragma unroll
            for (int t = 0; t < 2; t++)
                #pragma unroll
                for (int n = 0; n < 4; n++)
                    mma_f16(acc[t][n], a[t], bf[n]);
        }
    }
    CP_WAIT0;
    __syncthreads();

    // transpose-stage C (128cs x 64j) -> g_spart16[kc][(b,j)][cs]
    float* Cs = (float*)smc;
    #pragma unroll
    for (int t = 0; t < 2; t++) {
        #pragma unroll
        for (int n = 0; n < 4; n++) {
            int row = R + t * 16 + ar;
            int col = C + n * 8 + 2 * ac;
            Cs[col * 130 + row]            = acc[t][n][0];
            Cs[(col + 1) * 130 + row]      = acc[t][n][1];
            Cs[col * 130 + row + 8]        = acc[t][n][2];
            Cs[(col + 1) * 130 + row + 8]  = acc[t][n][3];
        }
    }
    __syncthreads();
    __half* dst = g_spart16 + (size_t)kc * SPART_SZ;
    #pragma unroll
    for (int l = 0; l < 32; l++) {
        int e = l * 256 + tid;
        int j = e >> 7, m = e & 127;
        dst[((b * NH + j) << 12) + m0 + m] = __float2half(Cs[j * 130 + m]);
    }
}

// ---------------------------------------------------------------------------
// 4) softmax: sum 4 fp16 split-K partials, softmax over compacted prefix
__global__ void k_softmax() {
    __shared__ float red[256];
    int row = blockIdx.x;
    int b = row >> 6;
    int cnt = g_cnt[b];
    const __half* p0 = g_spart16 + (size_t)row * SS;
    __half* sc = g_attnh + (size_t)row * SS;
    int tid = threadIdx.x;
    float v[16];
    float mx = -FLT_MAX;
    #pragma unroll
    for (int k = 0; k < 16; k++) {
        int s = k * 256 + tid;
        float val = -FLT_MAX;
        if (s < cnt)
            val = __half2float(p0[s]) + __half2float(p0[SPART_SZ + s])
                + __half2float(p0[2 * SPART_SZ + s]) + __half2float(p0[3 * SPART_SZ + s]);
        v[k] = val;
        mx = fmaxf(mx, val);
    }
    red[tid] = mx; __syncthreads();
    for (int o = 128; o; o >>= 1) { if (tid < o) red[tid] = fmaxf(red[tid], red[tid + o]); __syncthreads(); }
    mx = red[0]; __syncthreads();
    float sum = 0.f;
    #pragma unroll
    for (int k = 0; k < 16; k++) {
        int s = k * 256 + tid;
        v[k] = (s < cnt) ? __expf(v[k] - mx) : 0.f;
        sum += v[k];
    }
    red[tid] = sum; __syncthreads();
    for (int o = 128; o; o >>= 1) { if (tid < o) red[tid] += red[tid + o]; __syncthreads(); }
    float inv = 1.f / red[0];
    #pragma unroll
    for (int k = 0; k < 16; k++) sc[k * 256 + tid] = __float2half(v[k] * inv);
}

// ---------------------------------------------------------------------------
// 5) agg fp16: tile 64j x 128i, split-s x2, A via ldmatrix.x4,
//    B=H16c [s][i] via ldmatrix.x4.trans
#define AGA_B (64 * 80)              // 5120 B attn tile
#define AGB_STRIDE 272               // B row stride bytes (128 halves + 8 pad)
#define AGB_B (32 * AGB_STRIDE)      // 8704 B
#define AG_STAGE_B (AGA_B + AGB_B)   // 13824 B
__global__ void __launch_bounds__(256) k_agg() {
    extern __shared__ char smc[];
    int tid = threadIdx.x, lane = tid & 31, w = tid >> 5;
    int wm = w & 1, wn = w >> 1;       // 2 j-groups x 4 i-groups
    int R = wm * 32, C = wn * 32;
    int b = blockIdx.y;
    int i0 = blockIdx.x * 128;
    int sc_id = blockIdx.z;
    int ar = lane >> 2, ac = lane & 3;
    int cnt = g_cnt[b];
    int NIT_total = (cnt + 31) >> 5;
    int half = (NIT_total + 1) >> 1;
    int it0 = sc_id * half;
    int it1 = min(NIT_total, it0 + half);

    uint32_t smem_u32 = (uint32_t)__cvta_generic_to_shared(smc);

    float acc[2][4][4];
    #pragma unroll
    for (int t = 0; t < 2; t++)
        #pragma unroll
        for (int n = 0; n < 4; n++)
            #pragma unroll
            for (int q = 0; q < 4; q++) acc[t][n][q] = 0.f;

    const __half* Asrc = g_attnh + (size_t)b * NH * SS;
    const __half* Bsrc = g_H16c + (size_t)b * SS * HID + i0;

    int rrow = tid >> 2;               // 0..63 (attn rows)
    int rc8 = (tid & 3) * 8;
    int brow = tid >> 3;               // 0..31 (H rows)
    int bseg = tid & 7;                // 0..7

    auto issue = [&](int stage, int it) {
        int st = it * 32;
        uint32_t base = smem_u32 + stage * AG_STAGE_B;
        cp16(base + rrow * 80 + (tid & 3) * 16, Asrc + (size_t)rrow * SS + st + rc8);
        uint32_t bb = base + AGA_B + brow * AGB_STRIDE;
        const __half* hb = Bsrc + (size_t)(st + brow) * HID;
        cp16(bb + bseg * 16, hb + bseg * 8);
        cp16(bb + (bseg + 8) * 16, hb + (bseg + 8) * 8);
    };

    int lr16 = lane & 15;
    int lhi = lane >> 4;

    if (it0 < it1) {
        issue(0, it0); CP_COMMIT;
        if (it0 + 1 < it1) issue(1, it0 + 1); CP_COMMIT;
        if (it0 + 2 < it1) issue(2, it0 + 2); CP_COMMIT;
        for (int it = it0; it < it1; it++) {
            CP_WAIT2;
            __syncthreads();
            if (it + 3 < it1) issue((it - it0 + 3) & 3, it + 3);
            CP_COMMIT;
            int stg = (it - it0) & 3;
            uint32_t abase = smem_u32 + stg * AG_STAGE_B;
            uint32_t bbase = abase + AGA_B;
            #pragma unroll
            for (int ks = 0; ks < 2; ks++) {
                uint32_t colb = (uint32_t)(ks * 32 + lhi * 16);
                uint32_t a[2][4];
                #pragma unroll
                for (int t = 0; t < 2; t++)
                    ldm_x4(a[t], abase + (uint32_t)((R + t * 16 + lr16) * 80) + colb);
                uint32_t rowb = (uint32_t)((ks * 16 + lr16) * AGB_STRIDE);
                uint32_t rb0[4], rb1[4];
                ldm_x4t(rb0, bbase + rowb + (uint32_t)((C + lhi * 8) * 2));
                ldm_x4t(rb1, bbase + rowb + (uint32_t)((C + 16 + lhi * 8) * 2));
                uint32_t bf[4][2] = {{rb0[0], rb0[1]}, {rb0[2], rb0[3]},
                                     {rb1[0], rb1[1]}, {rb1[2], rb1[3]}};
                #pragma unroll
                for (int t = 0; t < 2; t++)
                    #pragma unroll
                    for (int n = 0; n < 4; n++)
                        mma_f16(acc[t][n], a[t], bf[n]);
            }
        }
    }

    float* dst = g_apart + sc_id * APART_SZ;
    #pragma unroll
    for (int t = 0; t < 2; t++) {
        #pragma unroll
        for (int n = 0; n < 4; n++) {
            int j = R + t * 16 + ar;
            int i = C + n * 8 + 2 * ac;
            float2 v0 = make_float2(acc[t][n][0], acc[t][n][1]);
            float2 v1 = make_float2(acc[t][n][2], acc[t][n][3]);
            *(float2*)&dst[(size_t)(b * NH + j) * HID + i0 + i]     = v0;
            *(float2*)&dst[(size_t)(b * NH + j + 8) * HID + i0 + i] = v1;
        }
    }
}

// ---------------------------------------------------------------------------
// 6) mid, split-K x4 with atomic epilogue; sums the 2 agg partials
__global__ void k_mid(const float* __restrict__ Wv) {
    __shared__ float As[8][65];
    __shared__ float Bs[64][65];
    int h = blockIdx.x, b = blockIdx.y, kc = blockIdx.z;
    int tid = threadIdx.x;
    float acc0 = 0.f, acc1 = 0.f;
    int o0 = tid, o1 = tid + 256;
    int n0 = o0 >> 6, d0 = o0 & 63;
    int n1 = o1 >> 6, d1 = o1 & 63;
    int k0 = kc * (HID / 4), k1 = k0 + HID / 4;
    for (int kt = k0; kt < k1; kt += 64) {
        {
            int e = tid; int r = e >> 6, c = e & 63;
            size_t ix = (size_t)(b * NH + h * SLOTS + r) * HID + kt + c;
            As[r][c] = g_apart[ix] + g_apart[APART_SZ + ix];
            e = tid + 256; r = e >> 6; c = e & 63;
            ix = (size_t)(b * NH + h * SLOTS + r) * HID + kt + c;
            As[r][c] = g_apart[ix] + g_apart[APART_SZ + ix];
        }
        #pragma unroll
        for (int l = 0; l < 16; l++) {
            int e = tid + l * 256;
            int r = e >> 6, c = e & 63;
            Bs[r][c] = Wv[(h * HD + r) * HID + kt + c];
        }
        __syncthreads();
        #pragma unroll
        for (int k = 0; k < 64; k++) {
            acc0 += As[n0][k] * Bs[d0][k];
            acc1 += As[n1][k] * Bs[d1][k];
        }
        __syncthreads();
    }
    atomicAdd(&g_mid[(b * SLOTS + n0) * BD + h * HD + d0], acc0);
    atomicAdd(&g_mid[(b * SLOTS + n1) * BD + h * HD + d1], acc1);
}

// ---------------------------------------------------------------------------
// 7) final, o-tile 64
__global__ void k_final(const float* __restrict__ Wo, float* __restrict__ out) {
    __shared__ float As[32][65];
    __shared__ float Bs[64][65];
    int tid = threadIdx.x;
    int tx = tid & 15, ty = tid >> 4;
    int o0 = blockIdx.x * 64;
    float acc[2][4] = {};
    for (int kt = 0; kt < BD; kt += 64) {
        #pragma unroll
        for (int l = 0; l < 8; l++) {
            int e = tid + l * 256;
            int r = e >> 6, c = e & 63;
            As[r][c] = g_mid[r * BD + kt + c];
        }
        #pragma unroll
        for (int l = 0; l < 16; l++) {
            int e = tid + l * 256;
            int r = e >> 6, c = e & 63;
            Bs[r][c] = Wo[(o0 + r) * BD + kt + c];
        }
        __syncthreads();
        #pragma unroll
        for (int k = 0; k < 64; k++) {
            float a[2], bb[4];
            #pragma unroll
            for (int x = 0; x < 2; x++) a[x] = As[ty * 2 + x][k];
            #pragma unroll
            for (int y = 0; y < 4; y++) bb[y] = Bs[tx * 4 + y][k];
            #pragma unroll
            for (int x = 0; x < 2; x++)
                #pragma unroll
                for (int y = 0; y < 4; y++) acc[x][y] += a[x] * bb[y];
        }
        __syncthreads();
    }
    #pragma unroll
    for (int x = 0; x < 2; x++)
        #pragma unroll
        for (int y = 0; y < 4; y++)
            out[(ty * 2 + x) * HID + o0 + tx * 4 + y] = acc[x][y];
}

// ---------------------------------------------------------------------------
extern "C" void kernel_launch(void* const* d_in, const int* in_sizes, int n_in,
                              void* d_out, int out_size) {
    const float* H    = (const float*)d_in[0];
    const int*   mask = (const int*)d_in[1];
    const float* ms   = (const float*)d_in[2];
    const float* Wq   = (const float*)d_in[3];
    const float* Wk   = (const float*)d_in[4];
    const float* Wv   = (const float*)d_in[5];
    const float* Wo   = (const float*)d_in[6];
    float* out = (float*)d_out;

    static int attr_done = 0;
    if (!attr_done) {
        cudaFuncSetAttribute(k_scores, cudaFuncAttributeMaxDynamicSharedMemorySize,
                             4 * SC_STAGE_B);
        cudaFuncSetAttribute(k_agg, cudaFuncAttributeMaxDynamicSharedMemorySize,
                             4 * AG_STAGE_B);
        attr_done = 1;
    }

    kA<<<BB + 512, 256>>>(mask, ms, Wq);
    kB<<<BB * SS + NH * 16, 256>>>(H, Wk);
    k_scores<<<dim3(SS / 128, BB, 4), 256, 4 * SC_STAGE_B>>>();
    k_softmax<<<BB * NH, 256>>>();
    k_agg   <<<dim3(HID / 128, BB, 2), 256, 4 * AG_STAGE_B>>>();
    k_mid   <<<dim3(HEADS, BB, 4), 256>>>(Wv);
    k_final <<<HID / 64, 256>>>(Wo, out);
}

// round 14
// speedup vs baseline: 1.2662x; 1.0190x over previous
#include <cuda_runtime.h>
#include <cuda_fp16.h>
#include <float.h>
#include <stdint.h>

#define HID 4096
#define SLOTS 8
#define HEADS 8
#define BD 512
#define HD 64
#define BB 4
#define SS 4096
#define NH 64   // HEADS*SLOTS

// Scratch (no allocations allowed)
__device__ float  g_Q[SLOTS * BD];
__device__ __half g_Qk16[NH * HID];              // fp16, scaled by 1/8
__device__ __half g_H16c[(size_t)BB * SS * HID]; // fp16 H, compacted rows
__device__ __half g_spart16[4 * BB * NH * SS];   // split-K score partials (fp16)
__device__ __half g_attnh[BB * NH * SS];         // attn probs (fp16)
__device__ float  g_apart[2 * BB * NH * HID];    // split-s agg partials
__device__ float  g_mid[BB * SLOTS * BD];
__device__ int    g_sidx[BB * SS];
__device__ int    g_cnt[BB];

#define SPART_SZ (BB * NH * SS)
#define APART_SZ (BB * NH * HID)

__device__ __forceinline__ void mma_f16(float* d, const uint32_t* a, const uint32_t* b) {
    asm volatile(
        "mma.sync.aligned.m16n8k16.row.col.f32.f16.f16.f32 "
        "{%0,%1,%2,%3}, {%4,%5,%6,%7}, {%8,%9}, {%0,%1,%2,%3};"
        : "+f"(d[0]), "+f"(d[1]), "+f"(d[2]), "+f"(d[3])
        : "r"(a[0]), "r"(a[1]), "r"(a[2]), "r"(a[3]), "r"(b[0]), "r"(b[1]));
}

__device__ __forceinline__ void ldm_x4(uint32_t* r, uint32_t addr) {
    asm volatile(
        "ldmatrix.sync.aligned.m8n8.x4.shared.b16 {%0,%1,%2,%3}, [%4];"
        : "=r"(r[0]), "=r"(r[1]), "=r"(r[2]), "=r"(r[3]) : "r"(addr));
}

__device__ __forceinline__ void ldm_x4t(uint32_t* r, uint32_t addr) {
    asm volatile(
        "ldmatrix.sync.aligned.m8n8.x4.trans.shared.b16 {%0,%1,%2,%3}, [%4];"
        : "=r"(r[0]), "=r"(r[1]), "=r"(r[2]), "=r"(r[3]) : "r"(addr));
}

__device__ __forceinline__ void cp16(uint32_t smem_dst, const void* gsrc) {
    asm volatile("cp.async.cg.shared.global [%0], [%1], 16;" :: "r"(smem_dst), "l"(gsrc));
}
#define CP_COMMIT asm volatile("cp.async.commit_group;")
#define CP_WAIT2  asm volatile("cp.async.wait_group 2;")
#define CP_WAIT0  asm volatile("cp.async.wait_group 0;")

// ---------------------------------------------------------------------------
// A) HORIZONTAL FUSION: blocks [0,BB) compact+zero g_mid; blocks [BB,..) qproj
__global__ void kA(const int* __restrict__ mask,
                   const float* __restrict__ ms, const float* __restrict__ Wq) {
    int tid = threadIdx.x;
    if (blockIdx.x < BB) {
        __shared__ int tsum[256];
        int b = blockIdx.x;
        const int* m = mask + b * SS;
        int loc[16], cnt = 0;
        #pragma unroll
        for (int k = 0; k < 16; k++) {
            loc[k] = (m[tid * 16 + k] != 0);
            cnt += loc[k];
        }
        tsum[tid] = cnt;
        __syncthreads();
        for (int o = 1; o < 256; o <<= 1) {
            int v = (tid >= o) ? tsum[tid - o] : 0;
            __syncthreads();
            tsum[tid] += v;
            __syncthreads();
        }
        int off = tsum[tid] - cnt;
        int total = tsum[255];
        int* out = g_sidx + b * SS;
        #pragma unroll
        for (int k = 0; k < 16; k++)
            if (loc[k]) out[off++] = tid * 16 + k;
        if (tid == 0) g_cnt[b] = total;
        float* gm = g_mid + b * 4096;
        #pragma unroll
        for (int k = 0; k < 16; k++) gm[k * 256 + tid] = 0.f;
    } else {
        int warp = ((blockIdx.x - BB) * 256 + tid) >> 5;
        int lane = tid & 31;
        if (warp >= SLOTS * BD) return;
        int n = warp / BD, c = warp % BD;
        const float* a = ms + n * HID;
        const float* w = Wq + c * HID;
        float acc = 0.f;
        for (int i = lane; i < HID; i += 32) acc += a[i] * w[i];
        #pragma unroll
        for (int off = 16; off; off >>= 1) acc += __shfl_down_sync(0xffffffffu, acc, off);
        if (lane == 0) g_Q[n * BD + c] = acc;
    }
}

// ---------------------------------------------------------------------------
// B) HORIZONTAL FUSION: blocks [0, BB*SS) conv (1 row/block, pad 128); rest qk
__global__ void kB(const float* __restrict__ H, const float* __restrict__ Wk) {
    cudaGridDependencySynchronize();
    int tid = threadIdx.x;
    int blk = blockIdx.x;
    if (blk < BB * SS) {
        int b = blk >> 12, cs = blk & 4095;
        int cnt = g_cnt[b];
        if (cs < cnt) {
            int s = g_sidx[b * SS + cs];
            const float4* src = (const float4*)(H + ((size_t)b * SS + s) * HID);
            uint2* dst = (uint2*)(g_H16c + ((size_t)b * SS + cs) * HID);
            float4 v0 = src[tid];
            float4 v1 = src[256 + tid];
            float4 v2 = src[512 + tid];
            float4 v3 = src[768 + tid];
            __half2 a0 = __floats2half2_rn(v0.x, v0.y), a1 = __floats2half2_rn(v0.z, v0.w);
            __half2 b0 = __floats2half2_rn(v1.x, v1.y), b1 = __floats2half2_rn(v1.z, v1.w);
            __half2 c0 = __floats2half2_rn(v2.x, v2.y), c1 = __floats2half2_rn(v2.z, v2.w);
            __half2 d0 = __floats2half2_rn(v3.x, v3.y), d1 = __floats2half2_rn(v3.z, v3.w);
            uint2 p0 = make_uint2(*(uint32_t*)&a0, *(uint32_t*)&a1);
            uint2 p1 = make_uint2(*(uint32_t*)&b0, *(uint32_t*)&b1);
            uint2 p2 = make_uint2(*(uint32_t*)&c0, *(uint32_t*)&c1);
            uint2 p3 = make_uint2(*(uint32_t*)&d0, *(uint32_t*)&d1);
            dst[tid] = p0; dst[256 + tid] = p1; dst[512 + tid] = p2; dst[768 + tid] = p3;
        } else if (cs < cnt + 128) {
            uint2* dst = (uint2*)(g_H16c + ((size_t)b * SS + cs) * HID);
            uint2 z = make_uint2(0u, 0u);
            dst[tid] = z; dst[256 + tid] = z; dst[512 + tid] = z; dst[768 + tid] = z;
        }
    } else {
        __shared__ float qs[HD];
        int idx = blk - BB * SS;
        int j = idx >> 4;            // 0..63
        int chunk = idx & 15;
        int h = j >> 3, n = j & 7;
        if (tid < HD) qs[tid] = g_Q[n * BD + h * HD + tid];
        __syncthreads();
        int i = chunk * 256 + tid;
        float acc = 0.f;
        #pragma unroll 8
        for (int d = 0; d < HD; d++) acc += qs[d] * Wk[(h * HD + d) * HID + i];
        g_Qk16[j * HID + i] = __float2half(acc * 0.125f);
    }
}

// ---------------------------------------------------------------------------
// 3) scores fp16: tile 128cs x 64j, split-K x4, 4-stage cp.async, ldmatrix
#define SC_A_B (128 * 80)           // 10240 B
#define SC_B_B (64 * 80)            // 5120 B
#define SC_STAGE_B (SC_A_B + SC_B_B)// 15360 B
__global__ void __launch_bounds__(256) k_scores() {
    cudaGridDependencySynchronize();
    extern __shared__ char smc[];
    int b = blockIdx.y, m0 = blockIdx.x * 128, kc = blockIdx.z;
    int cnt = g_cnt[b];
    if (m0 >= cnt) return;
    int tid = threadIdx.x, lane = tid & 31, w = tid >> 5;
    int wm = w & 3, wn = w >> 2;       // 4 m-groups x 2 n-groups
    int R = wm * 32, C = wn * 32;
    int ar = lane >> 2, ac = lane & 3;
    uint32_t smem_u32 = (uint32_t)__cvta_generic_to_shared(smc);

    float acc[2][4][4];
    #pragma unroll
    for (int t = 0; t < 2; t++)
        #pragma unroll
        for (int n = 0; n < 4; n++)
            #pragma unroll
            for (int q = 0; q < 4; q++) acc[t][n][q] = 0.f;

    int arow = tid >> 2;               // 0..63
    int aseg = tid & 3;                // 0..3 x16B
    const __half* Asrc = g_H16c + ((size_t)b * SS + m0) * HID + kc * 1024;
    const __half* Bsrc = g_Qk16 + kc * 1024;

    auto issue = [&](int stage, int it) {
        int st = it * 32;
        uint32_t base = smem_u32 + stage * SC_STAGE_B;
        cp16(base + arow * 80 + aseg * 16, Asrc + (size_t)arow * HID + st + aseg * 8);
        cp16(base + (arow + 64) * 80 + aseg * 16,
             Asrc + (size_t)(arow + 64) * HID + st + aseg * 8);
        cp16(base + SC_A_B + arow * 80 + aseg * 16,
             Bsrc + (size_t)arow * HID + st + aseg * 8);
    };

    int lr16 = lane & 15;
    int lhi = lane >> 4;

    const int NIT = 32;
    issue(0, 0); CP_COMMIT;
    issue(1, 1); CP_COMMIT;
    issue(2, 2); CP_COMMIT;
    for (int it = 0; it < NIT; it++) {
        CP_WAIT2;
        __syncthreads();
        if (it + 3 < NIT) issue((it + 3) & 3, it + 3);
        CP_COMMIT;
        uint32_t abase = smem_u32 + (it & 3) * SC_STAGE_B;
        uint32_t bbase = abase + SC_A_B;
        #pragma unroll
        for (int ks = 0; ks < 2; ks++) {
            uint32_t colb = (uint32_t)(ks * 32 + lhi * 16);
            uint32_t a[2][4];
            #pragma unroll
            for (int t = 0; t < 2; t++)
                ldm_x4(a[t], abase + (uint32_t)((R + t * 16 + lr16) * 80) + colb);
            uint32_t rbA[4], rbB[4];
            ldm_x4(rbA, bbase + (uint32_t)((C + lr16) * 80) + colb);
            ldm_x4(rbB, bbase + (uint32_t)((C + 16 + lr16) * 80) + colb);
            uint32_t bf[4][2] = {{rbA[0], rbA[2]}, {rbA[1], rbA[3]},
                                 {rbB[0], rbB[2]}, {rbB[1], rbB[3]}};
            #pragma unroll
            for (int t = 0; t < 2; t++)
                #pragma unroll
                for (int n = 0; n < 4; n++)
                    mma_f16(acc[t][n], a[t], bf[n]);
        }
    }
    CP_WAIT0;
    __syncthreads();

    // transpose-stage C (128cs x 64j) -> g_spart16[kc][(b,j)][cs]
    float* Cs = (float*)smc;
    #pragma unroll
    for (int t = 0; t < 2; t++) {
        #pragma unroll
        for (int n = 0; n < 4; n++) {
            int row = R + t * 16 + ar;
            int col = C + n * 8 + 2 * ac;
            Cs[col * 130 + row]            = acc[t][n][0];
            Cs[(col + 1) * 130 + row]      = acc[t][n][1];
            Cs[col * 130 + row + 8]        = acc[t][n][2];
            Cs[(col + 1) * 130 + row + 8]  = acc[t][n][3];
        }
    }
    __syncthreads();
    __half* dst = g_spart16 + (size_t)kc * SPART_SZ;
    #pragma unroll
    for (int l = 0; l < 32; l++) {
        int e = l * 256 + tid;
        int j = e >> 7, m = e & 127;
        dst[((b * NH + j) << 12) + m0 + m] = __float2half(Cs[j * 130 + m]);
    }
}

// ---------------------------------------------------------------------------
// 4) softmax: sum 4 fp16 split-K partials, softmax over compacted prefix
__global__ void k_softmax() {
    cudaGridDependencySynchronize();
    __shared__ float red[256];
    int row = blockIdx.x;
    int b = row >> 6;
    int cnt = g_cnt[b];
    const __half* p0 = g_spart16 + (size_t)row * SS;
    __half* sc = g_attnh + (size_t)row * SS;
    int tid = threadIdx.x;
    float v[16];
    float mx = -FLT_MAX;
    #pragma unroll
    for (int k = 0; k < 16; k++) {
        int s = k * 256 + tid;
        float val = -FLT_MAX;
        if (s < cnt)
            val = __half2float(p0[s]) + __half2float(p0[SPART_SZ + s])
                + __half2float(p0[2 * SPART_SZ + s]) + __half2float(p0[3 * SPART_SZ + s]);
        v[k] = val;
        mx = fmaxf(mx, val);
    }
    red[tid] = mx; __syncthreads();
    for (int o = 128; o; o >>= 1) { if (tid < o) red[tid] = fmaxf(red[tid], red[tid + o]); __syncthreads(); }
    mx = red[0]; __syncthreads();
    float sum = 0.f;
    #pragma unroll
    for (int k = 0; k < 16; k++) {
        int s = k * 256 + tid;
        v[k] = (s < cnt) ? __expf(v[k] - mx) : 0.f;
        sum += v[k];
    }
    red[tid] = sum; __syncthreads();
    for (int o = 128; o; o >>= 1) { if (tid < o) red[tid] += red[tid + o]; __syncthreads(); }
    float inv = 1.f / red[0];
    #pragma unroll
    for (int k = 0; k < 16; k++) sc[k * 256 + tid] = __float2half(v[k] * inv);
}

// ---------------------------------------------------------------------------
// 5) agg fp16: tile 64j x 128i, split-s x2, A via ldmatrix.x4,
//    B=H16c [s][i] via ldmatrix.x4.trans
#define AGA_B (64 * 80)              // 5120 B attn tile
#define AGB_STRIDE 272               // B row stride bytes (128 halves + 8 pad)
#define AGB_B (32 * AGB_STRIDE)      // 8704 B
#define AG_STAGE_B (AGA_B + AGB_B)   // 13824 B
__global__ void __launch_bounds__(256) k_agg() {
    cudaGridDependencySynchronize();
    extern __shared__ char smc[];
    int tid = threadIdx.x, lane = tid & 31, w = tid >> 5;
    int wm = w & 1, wn = w >> 1;       // 2 j-groups x 4 i-groups
    int R = wm * 32, C = wn * 32;
    int b = blockIdx.y;
    int i0 = blockIdx.x * 128;
    int sc_id = blockIdx.z;
    int ar = lane >> 2, ac = lane & 3;
    int cnt = g_cnt[b];
    int NIT_total = (cnt + 31) >> 5;
    int half = (NIT_total + 1) >> 1;
    int it0 = sc_id * half;
    int it1 = min(NIT_total, it0 + half);

    uint32_t smem_u32 = (uint32_t)__cvta_generic_to_shared(smc);

    float acc[2][4][4];
    #pragma unroll
    for (int t = 0; t < 2; t++)
        #pragma unroll
        for (int n = 0; n < 4; n++)
            #pragma unroll
            for (int q = 0; q < 4; q++) acc[t][n][q] = 0.f;

    const __half* Asrc = g_attnh + (size_t)b * NH * SS;
    const __half* Bsrc = g_H16c + (size_t)b * SS * HID + i0;

    int rrow = tid >> 2;               // 0..63 (attn rows)
    int rc8 = (tid & 3) * 8;
    int brow = tid >> 3;               // 0..31 (H rows)
    int bseg = tid & 7;                // 0..7

    auto issue = [&](int stage, int it) {
        int st = it * 32;
        uint32_t base = smem_u32 + stage * AG_STAGE_B;
        cp16(base + rrow * 80 + (tid & 3) * 16, Asrc + (size_t)rrow * SS + st + rc8);
        uint32_t bb = base + AGA_B + brow * AGB_STRIDE;
        const __half* hb = Bsrc + (size_t)(st + brow) * HID;
        cp16(bb + bseg * 16, hb + bseg * 8);
        cp16(bb + (bseg + 8) * 16, hb + (bseg + 8) * 8);
    };

    int lr16 = lane & 15;
    int lhi = lane >> 4;

    if (it0 < it1) {
        issue(0, it0); CP_COMMIT;
        if (it0 + 1 < it1) issue(1, it0 + 1); CP_COMMIT;
        if (it0 + 2 < it1) issue(2, it0 + 2); CP_COMMIT;
        for (int it = it0; it < it1; it++) {
            CP_WAIT2;
            __syncthreads();
            if (it + 3 < it1) issue((it - it0 + 3) & 3, it + 3);
            CP_COMMIT;
            int stg = (it - it0) & 3;
            uint32_t abase = smem_u32 + stg * AG_STAGE_B;
            uint32_t bbase = abase + AGA_B;
            #pragma unroll
            for (int ks = 0; ks < 2; ks++) {
                uint32_t colb = (uint32_t)(ks * 32 + lhi * 16);
                uint32_t a[2][4];
                #pragma unroll
                for (int t = 0; t < 2; t++)
                    ldm_x4(a[t], abase + (uint32_t)((R + t * 16 + lr16) * 80) + colb);
                uint32_t rowb = (uint32_t)((ks * 16 + lr16) * AGB_STRIDE);
                uint32_t rb0[4], rb1[4];
                ldm_x4t(rb0, bbase + rowb + (uint32_t)((C + lhi * 8) * 2));
                ldm_x4t(rb1, bbase + rowb + (uint32_t)((C + 16 + lhi * 8) * 2));
                uint32_t bf[4][2] = {{rb0[0], rb0[1]}, {rb0[2], rb0[3]},
                                     {rb1[0], rb1[1]}, {rb1[2], rb1[3]}};
                #pragma unroll
                for (int t = 0; t < 2; t++)
                    #pragma unroll
                    for (int n = 0; n < 4; n++)
                        mma_f16(acc[t][n], a[t], bf[n]);
            }
        }
    }

    float* dst = g_apart + sc_id * APART_SZ;
    #pragma unroll
    for (int t = 0; t < 2; t++) {
        #pragma unroll
        for (int n = 0; n < 4; n++) {
            int j = R + t * 16 + ar;
            int i = C + n * 8 + 2 * ac;
            float2 v0 = make_float2(acc[t][n][0], acc[t][n][1]);
            float2 v1 = make_float2(acc[t][n][2], acc[t][n][3]);
            *(float2*)&dst[(size_t)(b * NH + j) * HID + i0 + i]     = v0;
            *(float2*)&dst[(size_t)(b * NH + j + 8) * HID + i0 + i] = v1;
        }
    }
}

// ---------------------------------------------------------------------------
// 6) mid, split-K x4 with atomic epilogue; sums the 2 agg partials
__global__ void k_mid(const float* __restrict__ Wv) {
    cudaGridDependencySynchronize();
    __shared__ float As[8][65];
    __shared__ float Bs[64][65];
    int h = blockIdx.x, b = blockIdx.y, kc = blockIdx.z;
    int tid = threadIdx.x;
    float acc0 = 0.f, acc1 = 0.f;
    int o0 = tid, o1 = tid + 256;
    int n0 = o0 >> 6, d0 = o0 & 63;
    int n1 = o1 >> 6, d1 = o1 & 63;
    int k0 = kc * (HID / 4), k1 = k0 + HID / 4;
    for (int kt = k0; kt < k1; kt += 64) {
        {
            int e = tid; int r = e >> 6, c = e & 63;
            size_t ix = (size_t)(b * NH + h * SLOTS + r) * HID + kt + c;
            As[r][c] = g_apart[ix] + g_apart[APART_SZ + ix];
            e = tid + 256; r = e >> 6; c = e & 63;
            ix = (size_t)(b * NH + h * SLOTS + r) * HID + kt + c;
            As[r][c] = g_apart[ix] + g_apart[APART_SZ + ix];
        }
        #pragma unroll
        for (int l = 0; l < 16; l++) {
            int e = tid + l * 256;
            int r = e >> 6, c = e & 63;
            Bs[r][c] = Wv[(h * HD + r) * HID + kt + c];
        }
        __syncthreads();
        #pragma unroll
        for (int k = 0; k < 64; k++) {
            acc0 += As[n0][k] * Bs[d0][k];
            acc1 += As[n1][k] * Bs[d1][k];
        }
        __syncthreads();
    }
    atomicAdd(&g_mid[(b * SLOTS + n0) * BD + h * HD + d0], acc0);
    atomicAdd(&g_mid[(b * SLOTS + n1) * BD + h * HD + d1], acc1);
}

// ---------------------------------------------------------------------------
// 7) final, o-tile 64
__global__ void k_final(const float* __restrict__ Wo, float* __restrict__ out) {
    cudaGridDependencySynchronize();
    __shared__ float As[32][65];
    __shared__ float Bs[64][65];
    int tid = threadIdx.x;
    int tx = tid & 15, ty = tid >> 4;
    int o0 = blockIdx.x * 64;
    float acc[2][4] = {};
    for (int kt = 0; kt < BD; kt += 64) {
        #pragma unroll
        for (int l = 0; l < 8; l++) {
            int e = tid + l * 256;
            int r = e >> 6, c = e & 63;
            As[r][c] = g_mid[r * BD + kt + c];
        }
        #pragma unroll
        for (int l = 0; l < 16; l++) {
            int e = tid + l * 256;
            int r = e >> 6, c = e & 63;
            Bs[r][c] = Wo[(o0 + r) * BD + kt + c];
        }
        __syncthreads();
        #pragma unroll
        for (int k = 0; k < 64; k++) {
            float a[2], bb[4];
            #pragma unroll
            for (int x = 0; x < 2; x++) a[x] = As[ty * 2 + x][k];
            #pragma unroll
            for (int y = 0; y < 4; y++) bb[y] = Bs[tx * 4 + y][k];
            #pragma unroll
            for (int x = 0; x < 2; x++)
                #pragma unroll
                for (int y = 0; y < 4; y++) acc[x][y] += a[x] * bb[y];
        }
        __syncthreads();
    }
    #pragma unroll
    for (int x = 0; x < 2; x++)
        #pragma unroll
        for (int y = 0; y < 4; y++)
            out[(ty * 2 + x) * HID + o0 + tx * 4 + y] = acc[x][y];
}

// ---------------------------------------------------------------------------
template <typename K, typename... Args>
static void launch_pdl(K kern, dim3 grid, dim3 block, size_t smem, Args... args) {
    cudaLaunchConfig_t cfg = {};
    cfg.gridDim = grid;
    cfg.blockDim = block;
    cfg.dynamicSmemBytes = smem;
    cudaLaunchAttribute at[1];
    at[0].id = cudaLaunchAttributeProgrammaticStreamSerialization;
    at[0].val.programmaticStreamSerializationAllowed = 1;
    cfg.attrs = at;
    cfg.numAttrs = 1;
    cudaLaunchKernelEx(&cfg, kern, args...);
}

extern "C" void kernel_launch(void* const* d_in, const int* in_sizes, int n_in,
                              void* d_out, int out_size) {
    const float* H    = (const float*)d_in[0];
    const int*   mask = (const int*)d_in[1];
    const float* ms   = (const float*)d_in[2];
    const float* Wq   = (const float*)d_in[3];
    const float* Wk   = (const float*)d_in[4];
    const float* Wv   = (const float*)d_in[5];
    const float* Wo   = (const float*)d_in[6];
    float* out = (float*)d_out;

    static int attr_done = 0;
    if (!attr_done) {
        cudaFuncSetAttribute(k_scores, cudaFuncAttributeMaxDynamicSharedMemorySize,
                             4 * SC_STAGE_B);
        cudaFuncSetAttribute(k_agg, cudaFuncAttributeMaxDynamicSharedMemorySize,
                             4 * AG_STAGE_B);
        attr_done = 1;
    }

    kA<<<BB + 512, 256>>>(mask, ms, Wq);
    launch_pdl(kB, dim3(BB * SS + NH * 16), dim3(256), 0, H, Wk);
    launch_pdl(k_scores, dim3(SS / 128, BB, 4), dim3(256), 4 * SC_STAGE_B);
    launch_pdl(k_softmax, dim3(BB * NH), dim3(256), 0);
    launch_pdl(k_agg, dim3(HID / 128, BB, 2), dim3(256), 4 * AG_STAGE_B);
    launch_pdl(k_mid, dim3(HEADS, BB, 4), dim3(256), 0, Wv);
    launch_pdl(k_final, dim3(HID / 64), dim3(256), 0, Wo, out);
}